// round 13
// baseline (speedup 1.0000x reference)
#include <cuda_runtime.h>
#include <math.h>

// Problem dims (fixed by the reference)
#define B_  1024
#define D_  512
#define H_  2048
#define NSTEPS 16

// -------- device scratch (allocation-free: static __device__ globals) --------
__device__ float g_y   [B_ * D_];      // current state y (exact fp32)
__device__ float g_yr  [B_ * D_];      // RNA-tf32-rounded copy of y (MMA input)
__device__ float g_ytmp[B_ * D_];      // RNA-rounded y + c*k (MMA input)
__device__ float g_acc [B_ * D_];      // RK4 accumulator (exact fp32)
__device__ float g_h   [B_ * H_];      // RNA-rounded tanh activations
__device__ float g_W1r [D_ * H_];      // RNA-rounded W1
__device__ float g_W2r [H_ * D_];      // RNA-rounded W2
__device__ float g_part[8][B_ * D_];   // split-K partials for GEMM2 (x8)

// ---------------------------------------------------------------------------
__device__ __forceinline__ float rna_tf32(float x) {
    unsigned r;
    asm("cvt.rna.tf32.f32 %0, %1;" : "=r"(r) : "f"(x));
    return __uint_as_float(r);
}
__device__ __forceinline__ float fast_tanh(float x) {
    float y;
    asm("tanh.approx.f32 %0, %1;" : "=f"(y) : "f"(x));
    return y;
}
// mma.sync m16n8k8 tf32: D = A@B + C, fp32 accumulate. Inputs already tf32-exact.
__device__ __forceinline__ void mma_tf32(float* c, const unsigned* a, const unsigned* b) {
    asm volatile(
        "mma.sync.aligned.m16n8k8.row.col.f32.tf32.tf32.f32 "
        "{%0,%1,%2,%3}, {%4,%5,%6,%7}, {%8,%9}, {%0,%1,%2,%3};"
        : "+f"(c[0]), "+f"(c[1]), "+f"(c[2]), "+f"(c[3])
        : "r"(a[0]), "r"(a[1]), "r"(a[2]), "r"(a[3]),
          "r"(b[0]), "r"(b[1]));
}
__device__ __forceinline__ void cp_async16(float* smem_dst, const float* gmem_src) {
    unsigned s = (unsigned)__cvta_generic_to_shared(smem_dst);
    asm volatile("cp.async.ca.shared.global [%0], [%1], 16;\n" :: "r"(s), "l"(gmem_src));
}
__device__ __forceinline__ void cp_commit() {
    asm volatile("cp.async.commit_group;\n");
}
template <int N>
__device__ __forceinline__ void cp_wait() {
    asm volatile("cp.async.wait_group %0;\n" :: "n"(N));
}
// ---- PDL (programmatic dependent launch) primitives, sm_90+ ---------------
__device__ __forceinline__ void gdc_wait() {
    asm volatile("griddepcontrol.wait;" ::: "memory");
}
__device__ __forceinline__ void gdc_launch() {
    asm volatile("griddepcontrol.launch_dependents;");
}

// ---------------------------------------------------------------------------
__global__ void init_y_kernel(const float* __restrict__ x) {
    int i = blockIdx.x * blockDim.x + threadIdx.x;
    if (i < B_ * D_) {
        float v = x[i];
        g_y[i]  = v;
        g_yr[i] = rna_tf32(v);
    }
}
__global__ void prep_weights_kernel(const float* __restrict__ W1,
                                    const float* __restrict__ W2) {
    int i = blockIdx.x * blockDim.x + threadIdx.x;
    if (i < D_ * H_) {
        g_W1r[i] = rna_tf32(W1[i]);
        g_W2r[i] = rna_tf32(W2[i]);
    }
}

// ---------------------------------------------------------------------------
// Shared SMEM layout for both GEMMs (floats), dynamic 56,832 B per CTA:
//   A(s) at s*2560       (128 rows x stride 20)  s = 0..2
//   B(s) at 7680+s*2176  (16 rows x stride 136)
// Frag banks: A -> 20g + t4 (32 distinct); B -> 8*t4 + g (32 distinct).
#define ASLAB 2560
#define BOFF  7680
#define BSLAB 2176

// ---------------------------------------------------------------------------
// GEMM1 (R11 config — the faster one):
//   g_h[1024,2048] = rna( tanh( Ain[1024,512] @ W1r + b1 + t ) )
//   CTA 128x128, BK=16, 256 threads = 8 warps (2M x 4N), warp tile 64x32
//   (LDS/MMA = 1.5). 3-stage single-sync cp.async. Grid (16,8) = 128 CTAs.
__global__ __launch_bounds__(256) void gemm1_tanh(
    const float* __restrict__ b1, float t, int in_sel)
{
    extern __shared__ float S[];

    const float* __restrict__ Ain = in_sel ? g_ytmp : g_yr;
    const float* __restrict__ W1  = g_W1r;

    const int tid  = threadIdx.x;
    const int lane = tid & 31;
    const int warp = tid >> 5;
    const int g    = lane >> 2;
    const int t4   = lane & 3;
    const int wm   = warp & 1;      // m offset wm*64
    const int wn   = warp >> 1;     // n offset wn*32

    const int bn0 = blockIdx.x * 128;
    const int bm0 = blockIdx.y * 128;

    auto load_slab = [&](int k0, int s) {
#pragma unroll
        for (int i = 0; i < 2; i++) {
            int id = tid + 256 * i;
            int r = id >> 2, c = (id & 3) * 4;
            cp_async16(&S[s * ASLAB + r * 20 + c],
                       &Ain[(size_t)(bm0 + r) * D_ + k0 + c]);
        }
#pragma unroll
        for (int i = 0; i < 2; i++) {
            int id = tid + 256 * i;
            int r = id >> 5, c = (id & 31) * 4;
            cp_async16(&S[BOFF + s * BSLAB + r * 136 + c],
                       &W1[(size_t)(k0 + r) * H_ + bn0 + c]);
        }
        cp_commit();
    };

    float c[4][4][4];
#pragma unroll
    for (int i = 0; i < 4; i++)
#pragma unroll
        for (int j = 0; j < 4; j++)
#pragma unroll
            for (int e = 0; e < 4; e++) c[i][j][e] = 0.f;

    gdc_wait();   // PDL: previous kernel's writes (g_ytmp/g_yr) now visible

    const int NS = D_ / 16;   // 32 slabs
    load_slab(0, 0);
    load_slab(16, 1);

    for (int si = 0; si < NS; si++) {
        if (si + 1 < NS) cp_wait<1>(); else cp_wait<0>();
        __syncthreads();
        if (si + 2 < NS) load_slab((si + 2) * 16, (si + 2) % 3);

        const unsigned* Asu = reinterpret_cast<const unsigned*>(&S[(si % 3) * ASLAB]);
        const unsigned* Bsu = reinterpret_cast<const unsigned*>(&S[BOFF + (si % 3) * BSLAB]);
#pragma unroll
        for (int kk = 0; kk < 16; kk += 8) {
            unsigned a[4][4], b[4][2];
#pragma unroll
            for (int mt = 0; mt < 4; mt++) {
                int m0 = wm * 64 + mt * 16 + g;
                a[mt][0] = Asu[(m0)     * 20 + kk + t4];
                a[mt][1] = Asu[(m0 + 8) * 20 + kk + t4];
                a[mt][2] = Asu[(m0)     * 20 + kk + t4 + 4];
                a[mt][3] = Asu[(m0 + 8) * 20 + kk + t4 + 4];
            }
#pragma unroll
            for (int nt = 0; nt < 4; nt++) {
                int n0 = wn * 32 + nt * 8 + g;
                b[nt][0] = Bsu[(kk + t4)     * 136 + n0];
                b[nt][1] = Bsu[(kk + t4 + 4) * 136 + n0];
            }
#pragma unroll
            for (int mt = 0; mt < 4; mt++)
#pragma unroll
                for (int nt = 0; nt < 4; nt++)
                    mma_tf32(c[mt][nt], a[mt], b[nt]);
        }
    }

    gdc_launch();   // PDL: let gemm2 start launching into our drain

    // epilogue: rna(tanh(c + b1[n] + t)) -> g_h
#pragma unroll
    for (int mt = 0; mt < 4; mt++) {
        int row0 = bm0 + wm * 64 + mt * 16 + g;
#pragma unroll
        for (int nt = 0; nt < 4; nt++) {
            int col = bn0 + wn * 32 + nt * 8 + 2 * t4;
            float bb0 = b1[col] + t, bb1 = b1[col + 1] + t;
            float2 v0, v1;
            v0.x = rna_tf32(fast_tanh(c[mt][nt][0] + bb0));
            v0.y = rna_tf32(fast_tanh(c[mt][nt][1] + bb1));
            v1.x = rna_tf32(fast_tanh(c[mt][nt][2] + bb0));
            v1.y = rna_tf32(fast_tanh(c[mt][nt][3] + bb1));
            *reinterpret_cast<float2*>(&g_h[(size_t)row0 * H_ + col])       = v0;
            *reinterpret_cast<float2*>(&g_h[(size_t)(row0 + 8) * H_ + col]) = v1;
        }
    }
}

// ---------------------------------------------------------------------------
// GEMM2 split-K x8 (R12 config, measured 21.95us):
//   partial[z][1024,512] = g_h[:, z*256:(z+1)*256] @ W2r[z*256:(z+1)*256, :]
//   CTA 128x128, K-slice 256, BK=16, 256 threads, warp tile 64x32.
//   Grid (4,8,8) = 256 CTAs.
__global__ __launch_bounds__(256) void gemm2_splitk()
{
    extern __shared__ float S[];

    const float* __restrict__ W2 = g_W2r;

    const int tid  = threadIdx.x;
    const int lane = tid & 31;
    const int warp = tid >> 5;
    const int g    = lane >> 2;
    const int t4   = lane & 3;
    const int wm   = warp & 1;      // m offset wm*64
    const int wn   = warp >> 1;     // n offset wn*32

    const int bn0 = blockIdx.x * 128;
    const int bm0 = blockIdx.y * 128;
    const int kb  = blockIdx.z * (H_ / 8);   // K-slice base (256 wide)

    auto load_slab = [&](int k0, int s) {
#pragma unroll
        for (int i = 0; i < 2; i++) {
            int id = tid + 256 * i;
            int r = id >> 2, c = (id & 3) * 4;
            cp_async16(&S[s * ASLAB + r * 20 + c],
                       &g_h[(size_t)(bm0 + r) * H_ + kb + k0 + c]);
        }
#pragma unroll
        for (int i = 0; i < 2; i++) {
            int id = tid + 256 * i;
            int r = id >> 5, c = (id & 31) * 4;
            cp_async16(&S[BOFF + s * BSLAB + r * 136 + c],
                       &W2[(size_t)(kb + k0 + r) * D_ + bn0 + c]);
        }
        cp_commit();
    };

    float c[4][4][4];
#pragma unroll
    for (int i = 0; i < 4; i++)
#pragma unroll
        for (int j = 0; j < 4; j++)
#pragma unroll
            for (int e = 0; e < 4; e++) c[i][j][e] = 0.f;

    gdc_wait();   // PDL: gemm1's g_h writes now visible

    const int NS = (H_ / 8) / 16;   // 16 slabs
    load_slab(0, 0);
    load_slab(16, 1);

    for (int si = 0; si < NS; si++) {
        if (si + 1 < NS) cp_wait<1>(); else cp_wait<0>();
        __syncthreads();
        if (si + 2 < NS) load_slab((si + 2) * 16, (si + 2) % 3);

        const unsigned* Asu = reinterpret_cast<const unsigned*>(&S[(si % 3) * ASLAB]);
        const unsigned* Bsu = reinterpret_cast<const unsigned*>(&S[BOFF + (si % 3) * BSLAB]);
#pragma unroll
        for (int kk = 0; kk < 16; kk += 8) {
            unsigned a[4][4], b[4][2];
#pragma unroll
            for (int mt = 0; mt < 4; mt++) {
                int m0 = wm * 64 + mt * 16 + g;
                a[mt][0] = Asu[(m0)     * 20 + kk + t4];
                a[mt][1] = Asu[(m0 + 8) * 20 + kk + t4];
                a[mt][2] = Asu[(m0)     * 20 + kk + t4 + 4];
                a[mt][3] = Asu[(m0 + 8) * 20 + kk + t4 + 4];
            }
#pragma unroll
            for (int nt = 0; nt < 4; nt++) {
                int n0 = wn * 32 + nt * 8 + g;
                b[nt][0] = Bsu[(kk + t4)     * 136 + n0];
                b[nt][1] = Bsu[(kk + t4 + 4) * 136 + n0];
            }
#pragma unroll
            for (int mt = 0; mt < 4; mt++)
#pragma unroll
                for (int nt = 0; nt < 4; nt++)
                    mma_tf32(c[mt][nt], a[mt], b[nt]);
        }
    }

    gdc_launch();   // PDL: let rk4_epi start launching

    // write raw partial tile
    float* __restrict__ P = g_part[blockIdx.z];
#pragma unroll
    for (int mt = 0; mt < 4; mt++) {
        int row0 = bm0 + wm * 64 + mt * 16 + g;
#pragma unroll
        for (int nt = 0; nt < 4; nt++) {
            int col = bn0 + wn * 32 + nt * 8 + 2 * t4;
            *reinterpret_cast<float2*>(&P[(size_t)row0 * D_ + col]) =
                make_float2(c[mt][nt][0], c[mt][nt][1]);
            *reinterpret_cast<float2*>(&P[(size_t)(row0 + 8) * D_ + col]) =
                make_float2(c[mt][nt][2], c[mt][nt][3]);
        }
    }
}

// ---------------------------------------------------------------------------
// RK4 epilogue: kv = sum of 8 partials + b2; apply stage update.
// mode: 0 k1 / 1 k2 / 2 k3 / 3 k4 / 4 k4-final(write d_out)
__global__ __launch_bounds__(256) void rk4_epi(
    const float* __restrict__ b2, float dt, int mode, float* __restrict__ yout)
{
    const int i4 = blockIdx.x * blockDim.x + threadIdx.x;   // 0..131071
    const int i  = i4 * 4;
    const int col = i & (D_ - 1);

    gdc_wait();     // PDL: gemm2 partials now visible
    gdc_launch();   // PDL: next gemm1 may launch (it waits on our completion)

    float kv[4] = {0.f, 0.f, 0.f, 0.f};
#pragma unroll
    for (int z = 0; z < 8; z++) {
        float4 p = *reinterpret_cast<const float4*>(&g_part[z][i]);
        kv[0] += p.x; kv[1] += p.y; kv[2] += p.z; kv[3] += p.w;
    }
    float4 bb = *reinterpret_cast<const float4*>(&b2[col]);
    kv[0] += bb.x; kv[1] += bb.y; kv[2] += bb.z; kv[3] += bb.w;

    const float half_dt  = 0.5f * dt;
    const float sixth_dt = dt * (1.0f / 6.0f);

    float4 y = *reinterpret_cast<const float4*>(&g_y[i]);
    float yv[4] = {y.x, y.y, y.z, y.w};

    if (mode == 0) {
        float4 ac, yt;
        ac.x = kv[0]; ac.y = kv[1]; ac.z = kv[2]; ac.w = kv[3];
        yt.x = rna_tf32(yv[0] + half_dt * kv[0]);
        yt.y = rna_tf32(yv[1] + half_dt * kv[1]);
        yt.z = rna_tf32(yv[2] + half_dt * kv[2]);
        yt.w = rna_tf32(yv[3] + half_dt * kv[3]);
        *reinterpret_cast<float4*>(&g_acc[i])  = ac;
        *reinterpret_cast<float4*>(&g_ytmp[i]) = yt;
    } else if (mode == 1 || mode == 2) {
        float4 ac = *reinterpret_cast<const float4*>(&g_acc[i]);
        ac.x += 2.f * kv[0]; ac.y += 2.f * kv[1];
        ac.z += 2.f * kv[2]; ac.w += 2.f * kv[3];
        float step = (mode == 1) ? half_dt : dt;
        float4 yt;
        yt.x = rna_tf32(yv[0] + step * kv[0]);
        yt.y = rna_tf32(yv[1] + step * kv[1]);
        yt.z = rna_tf32(yv[2] + step * kv[2]);
        yt.w = rna_tf32(yv[3] + step * kv[3]);
        *reinterpret_cast<float4*>(&g_acc[i])  = ac;
        *reinterpret_cast<float4*>(&g_ytmp[i]) = yt;
    } else if (mode == 3) {
        float4 ac = *reinterpret_cast<const float4*>(&g_acc[i]);
        float4 yn, yr;
        yn.x = yv[0] + sixth_dt * (ac.x + kv[0]);
        yn.y = yv[1] + sixth_dt * (ac.y + kv[1]);
        yn.z = yv[2] + sixth_dt * (ac.z + kv[2]);
        yn.w = yv[3] + sixth_dt * (ac.w + kv[3]);
        yr.x = rna_tf32(yn.x); yr.y = rna_tf32(yn.y);
        yr.z = rna_tf32(yn.z); yr.w = rna_tf32(yn.w);
        *reinterpret_cast<float4*>(&g_y[i])  = yn;
        *reinterpret_cast<float4*>(&g_yr[i]) = yr;
    } else {
        float4 ac = *reinterpret_cast<const float4*>(&g_acc[i]);
        float4 o;
        o.x = yv[0] + sixth_dt * (ac.x + kv[0]);
        o.y = yv[1] + sixth_dt * (ac.y + kv[1]);
        o.z = yv[2] + sixth_dt * (ac.z + kv[2]);
        o.w = yv[3] + sixth_dt * (ac.w + kv[3]);
        *reinterpret_cast<float4*>(&yout[i]) = o;
    }
}

// ---------------------------------------------------------------------------
static inline void launch_pdl(void* fn, dim3 grid, dim3 block, size_t smem,
                              void** args)
{
    cudaLaunchConfig_t cfg = {};
    cfg.gridDim = grid;
    cfg.blockDim = block;
    cfg.dynamicSmemBytes = smem;
    cfg.stream = 0;
    cudaLaunchAttribute attr[1];
    attr[0].id = cudaLaunchAttributeProgrammaticStreamSerialization;
    attr[0].val.programmaticStreamSerializationAllowed = 1;
    cfg.attrs = attr;
    cfg.numAttrs = 1;
    cudaLaunchKernelExC(&cfg, fn, args);
}

extern "C" void kernel_launch(void* const* d_in, const int* in_sizes, int n_in,
                              void* d_out, int out_size)
{
    const float* x  = (const float*)d_in[0];   // [1024, 512]
    const float* W1 = (const float*)d_in[1];   // [512, 2048]
    const float* b1 = (const float*)d_in[2];   // [2048]
    const float* W2 = (const float*)d_in[3];   // [2048, 512]
    const float* b2 = (const float*)d_in[4];   // [512]
    float* out = (float*)d_out;                // [1024, 512]

    const float dt = 1.0f / (float)NSTEPS;

    const size_t SMEM_G = (3 * ASLAB + 3 * BSLAB) * 4;   // 56,832 B
    cudaFuncSetAttribute(gemm1_tanh,   cudaFuncAttributeMaxDynamicSharedMemorySize, (int)SMEM_G);
    cudaFuncSetAttribute(gemm2_splitk, cudaFuncAttributeMaxDynamicSharedMemorySize, (int)SMEM_G);

    init_y_kernel<<<(B_ * D_ + 255) / 256, 256>>>(x);
    prep_weights_kernel<<<(D_ * H_ + 255) / 256, 256>>>(W1, W2);

    dim3 grid1(H_ / 128, B_ / 128);        // (16,8)  = 128 CTAs
    dim3 grid2(D_ / 128, B_ / 128, 8);     // (4,8,8) = 256 CTAs
    dim3 gridE((B_ * D_ / 4) / 256);       // 512 blocks
    dim3 blk(256, 1, 1);

    for (int s = 0; s < NSTEPS; s++) {
        float t0 = dt * (float)s;
        float th = t0 + 0.5f * dt;
        float t1 = t0 + dt;

        float targ[4] = {t0, th, th, t1};
        int   insel[4] = {0, 1, 1, 1};
        int   modes[4] = {0, 1, 2, (s == NSTEPS - 1) ? 4 : 3};

        for (int st = 0; st < 4; st++) {
            int   is = insel[st];
            float tv = targ[st];
            int   md = modes[st];

            void* a1[] = {(void*)&b1, (void*)&tv, (void*)&is};
            launch_pdl((void*)gemm1_tanh, grid1, blk, SMEM_G, a1);

            void* a2[] = {};
            launch_pdl((void*)gemm2_splitk, grid2, blk, SMEM_G, a2);

            void* a3[] = {(void*)&b2, (void*)&dt, (void*)&md, (void*)&out};
            launch_pdl((void*)rk4_epi, gridE, blk, 0, a3);
        }
    }
}

// round 14
// speedup vs baseline: 1.3328x; 1.3328x over previous
#include <cuda_runtime.h>
#include <math.h>

// Problem dims (fixed by the reference)
#define B_  1024
#define D_  512
#define H_  2048
#define NSTEPS 16

// -------- device scratch (allocation-free: static __device__ globals) --------
__device__ float g_y   [B_ * D_];      // current state y (exact fp32)
__device__ float g_yr  [B_ * D_];      // RNA-tf32-rounded copy of y (MMA input)
__device__ float g_ytmp[B_ * D_];      // RNA-rounded y + c*k (MMA input)
__device__ float g_acc [B_ * D_];      // RK4 accumulator (exact fp32)
__device__ float g_h   [B_ * H_];      // RNA-rounded tanh activations
__device__ float g_W1r [D_ * H_];      // RNA-rounded W1
__device__ float g_W2r [H_ * D_];      // RNA-rounded W2
__device__ float g_part[8][B_ * D_];   // split-K partials for GEMM2 (x8)

// ---------------------------------------------------------------------------
__device__ __forceinline__ float rna_tf32(float x) {
    unsigned r;
    asm("cvt.rna.tf32.f32 %0, %1;" : "=r"(r) : "f"(x));
    return __uint_as_float(r);
}
__device__ __forceinline__ float fast_tanh(float x) {
    float y;
    asm("tanh.approx.f32 %0, %1;" : "=f"(y) : "f"(x));
    return y;
}
// mma.sync m16n8k8 tf32: D = A@B + C, fp32 accumulate. Inputs already tf32-exact.
__device__ __forceinline__ void mma_tf32(float* c, const unsigned* a, const unsigned* b) {
    asm volatile(
        "mma.sync.aligned.m16n8k8.row.col.f32.tf32.tf32.f32 "
        "{%0,%1,%2,%3}, {%4,%5,%6,%7}, {%8,%9}, {%0,%1,%2,%3};"
        : "+f"(c[0]), "+f"(c[1]), "+f"(c[2]), "+f"(c[3])
        : "r"(a[0]), "r"(a[1]), "r"(a[2]), "r"(a[3]),
          "r"(b[0]), "r"(b[1]));
}
__device__ __forceinline__ void cp_async16(float* smem_dst, const float* gmem_src) {
    unsigned s = (unsigned)__cvta_generic_to_shared(smem_dst);
    asm volatile("cp.async.ca.shared.global [%0], [%1], 16;\n" :: "r"(s), "l"(gmem_src));
}
__device__ __forceinline__ void cp_commit() {
    asm volatile("cp.async.commit_group;\n");
}
template <int N>
__device__ __forceinline__ void cp_wait() {
    asm volatile("cp.async.wait_group %0;\n" :: "n"(N));
}

// ---------------------------------------------------------------------------
__global__ void init_y_kernel(const float* __restrict__ x) {
    int i = blockIdx.x * blockDim.x + threadIdx.x;
    if (i < B_ * D_) {
        float v = x[i];
        g_y[i]  = v;
        g_yr[i] = rna_tf32(v);
    }
}
__global__ void prep_weights_kernel(const float* __restrict__ W1,
                                    const float* __restrict__ W2) {
    int i = blockIdx.x * blockDim.x + threadIdx.x;
    if (i < D_ * H_) {
        g_W1r[i] = rna_tf32(W1[i]);
        g_W2r[i] = rna_tf32(W2[i]);
    }
}

// ---------------------------------------------------------------------------
// Shared SMEM layout for both GEMMs (floats), dynamic 56,832 B per CTA:
//   A(s) at s*2560       (128 rows x stride 20)  s = 0..2
//   B(s) at 7680+s*2176  (16 rows x stride 136)
// Frag banks: A -> 20g + t4 (32 distinct); B -> 8*t4 + g (32 distinct).
#define ASLAB 2560
#define BOFF  7680
#define BSLAB 2176

// ---------------------------------------------------------------------------
// GEMM1 (R11 config — fastest measured gemm1):
//   g_h[1024,2048] = rna( tanh( Ain[1024,512] @ W1r + b1 + t ) )
//   CTA 128x128, BK=16, 256 threads = 8 warps (2M x 4N), warp tile 64x32
//   (LDS/MMA = 1.5). 3-stage single-sync cp.async. Grid (16,8) = 128 CTAs.
__global__ __launch_bounds__(256) void gemm1_tanh(
    const float* __restrict__ b1, float t, int in_sel)
{
    extern __shared__ float S[];

    const float* __restrict__ Ain = in_sel ? g_ytmp : g_yr;
    const float* __restrict__ W1  = g_W1r;

    const int tid  = threadIdx.x;
    const int lane = tid & 31;
    const int warp = tid >> 5;
    const int g    = lane >> 2;
    const int t4   = lane & 3;
    const int wm   = warp & 1;      // m offset wm*64
    const int wn   = warp >> 1;     // n offset wn*32

    const int bn0 = blockIdx.x * 128;
    const int bm0 = blockIdx.y * 128;

    auto load_slab = [&](int k0, int s) {
#pragma unroll
        for (int i = 0; i < 2; i++) {
            int id = tid + 256 * i;
            int r = id >> 2, c = (id & 3) * 4;
            cp_async16(&S[s * ASLAB + r * 20 + c],
                       &Ain[(size_t)(bm0 + r) * D_ + k0 + c]);
        }
#pragma unroll
        for (int i = 0; i < 2; i++) {
            int id = tid + 256 * i;
            int r = id >> 5, c = (id & 31) * 4;
            cp_async16(&S[BOFF + s * BSLAB + r * 136 + c],
                       &W1[(size_t)(k0 + r) * H_ + bn0 + c]);
        }
        cp_commit();
    };

    float c[4][4][4];
#pragma unroll
    for (int i = 0; i < 4; i++)
#pragma unroll
        for (int j = 0; j < 4; j++)
#pragma unroll
            for (int e = 0; e < 4; e++) c[i][j][e] = 0.f;

    const int NS = D_ / 16;   // 32 slabs
    load_slab(0, 0);
    load_slab(16, 1);

    for (int si = 0; si < NS; si++) {
        if (si + 1 < NS) cp_wait<1>(); else cp_wait<0>();
        __syncthreads();
        if (si + 2 < NS) load_slab((si + 2) * 16, (si + 2) % 3);

        const unsigned* Asu = reinterpret_cast<const unsigned*>(&S[(si % 3) * ASLAB]);
        const unsigned* Bsu = reinterpret_cast<const unsigned*>(&S[BOFF + (si % 3) * BSLAB]);
#pragma unroll
        for (int kk = 0; kk < 16; kk += 8) {
            unsigned a[4][4], b[4][2];
#pragma unroll
            for (int mt = 0; mt < 4; mt++) {
                int m0 = wm * 64 + mt * 16 + g;
                a[mt][0] = Asu[(m0)     * 20 + kk + t4];
                a[mt][1] = Asu[(m0 + 8) * 20 + kk + t4];
                a[mt][2] = Asu[(m0)     * 20 + kk + t4 + 4];
                a[mt][3] = Asu[(m0 + 8) * 20 + kk + t4 + 4];
            }
#pragma unroll
            for (int nt = 0; nt < 4; nt++) {
                int n0 = wn * 32 + nt * 8 + g;
                b[nt][0] = Bsu[(kk + t4)     * 136 + n0];
                b[nt][1] = Bsu[(kk + t4 + 4) * 136 + n0];
            }
#pragma unroll
            for (int mt = 0; mt < 4; mt++)
#pragma unroll
                for (int nt = 0; nt < 4; nt++)
                    mma_tf32(c[mt][nt], a[mt], b[nt]);
        }
    }

    // epilogue: rna(tanh(c + b1[n] + t)) -> g_h
#pragma unroll
    for (int mt = 0; mt < 4; mt++) {
        int row0 = bm0 + wm * 64 + mt * 16 + g;
#pragma unroll
        for (int nt = 0; nt < 4; nt++) {
            int col = bn0 + wn * 32 + nt * 8 + 2 * t4;
            float bb0 = b1[col] + t, bb1 = b1[col + 1] + t;
            float2 v0, v1;
            v0.x = rna_tf32(fast_tanh(c[mt][nt][0] + bb0));
            v0.y = rna_tf32(fast_tanh(c[mt][nt][1] + bb1));
            v1.x = rna_tf32(fast_tanh(c[mt][nt][2] + bb0));
            v1.y = rna_tf32(fast_tanh(c[mt][nt][3] + bb1));
            *reinterpret_cast<float2*>(&g_h[(size_t)row0 * H_ + col])       = v0;
            *reinterpret_cast<float2*>(&g_h[(size_t)(row0 + 8) * H_ + col]) = v1;
        }
    }
}

// ---------------------------------------------------------------------------
// GEMM2 split-K x8 (fastest measured gemm2, 21.95us):
//   partial[z][1024,512] = g_h[:, z*256:(z+1)*256] @ W2r[z*256:(z+1)*256, :]
//   CTA 128x128, K-slice 256, BK=16, 256 threads, warp tile 64x32.
//   Grid (4,8,8) = 256 CTAs.
__global__ __launch_bounds__(256) void gemm2_splitk()
{
    extern __shared__ float S[];

    const float* __restrict__ W2 = g_W2r;

    const int tid  = threadIdx.x;
    const int lane = tid & 31;
    const int warp = tid >> 5;
    const int g    = lane >> 2;
    const int t4   = lane & 3;
    const int wm   = warp & 1;      // m offset wm*64
    const int wn   = warp >> 1;     // n offset wn*32

    const int bn0 = blockIdx.x * 128;
    const int bm0 = blockIdx.y * 128;
    const int kb  = blockIdx.z * (H_ / 8);   // K-slice base (256 wide)

    auto load_slab = [&](int k0, int s) {
#pragma unroll
        for (int i = 0; i < 2; i++) {
            int id = tid + 256 * i;
            int r = id >> 2, c = (id & 3) * 4;
            cp_async16(&S[s * ASLAB + r * 20 + c],
                       &g_h[(size_t)(bm0 + r) * H_ + kb + k0 + c]);
        }
#pragma unroll
        for (int i = 0; i < 2; i++) {
            int id = tid + 256 * i;
            int r = id >> 5, c = (id & 31) * 4;
            cp_async16(&S[BOFF + s * BSLAB + r * 136 + c],
                       &W2[(size_t)(kb + k0 + r) * D_ + bn0 + c]);
        }
        cp_commit();
    };

    float c[4][4][4];
#pragma unroll
    for (int i = 0; i < 4; i++)
#pragma unroll
        for (int j = 0; j < 4; j++)
#pragma unroll
            for (int e = 0; e < 4; e++) c[i][j][e] = 0.f;

    const int NS = (H_ / 8) / 16;   // 16 slabs
    load_slab(0, 0);
    load_slab(16, 1);

    for (int si = 0; si < NS; si++) {
        if (si + 1 < NS) cp_wait<1>(); else cp_wait<0>();
        __syncthreads();
        if (si + 2 < NS) load_slab((si + 2) * 16, (si + 2) % 3);

        const unsigned* Asu = reinterpret_cast<const unsigned*>(&S[(si % 3) * ASLAB]);
        const unsigned* Bsu = reinterpret_cast<const unsigned*>(&S[BOFF + (si % 3) * BSLAB]);
#pragma unroll
        for (int kk = 0; kk < 16; kk += 8) {
            unsigned a[4][4], b[4][2];
#pragma unroll
            for (int mt = 0; mt < 4; mt++) {
                int m0 = wm * 64 + mt * 16 + g;
                a[mt][0] = Asu[(m0)     * 20 + kk + t4];
                a[mt][1] = Asu[(m0 + 8) * 20 + kk + t4];
                a[mt][2] = Asu[(m0)     * 20 + kk + t4 + 4];
                a[mt][3] = Asu[(m0 + 8) * 20 + kk + t4 + 4];
            }
#pragma unroll
            for (int nt = 0; nt < 4; nt++) {
                int n0 = wn * 32 + nt * 8 + g;
                b[nt][0] = Bsu[(kk + t4)     * 136 + n0];
                b[nt][1] = Bsu[(kk + t4 + 4) * 136 + n0];
            }
#pragma unroll
            for (int mt = 0; mt < 4; mt++)
#pragma unroll
                for (int nt = 0; nt < 4; nt++)
                    mma_tf32(c[mt][nt], a[mt], b[nt]);
        }
    }

    // write raw partial tile
    float* __restrict__ P = g_part[blockIdx.z];
#pragma unroll
    for (int mt = 0; mt < 4; mt++) {
        int row0 = bm0 + wm * 64 + mt * 16 + g;
#pragma unroll
        for (int nt = 0; nt < 4; nt++) {
            int col = bn0 + wn * 32 + nt * 8 + 2 * t4;
            *reinterpret_cast<float2*>(&P[(size_t)row0 * D_ + col]) =
                make_float2(c[mt][nt][0], c[mt][nt][1]);
            *reinterpret_cast<float2*>(&P[(size_t)(row0 + 8) * D_ + col]) =
                make_float2(c[mt][nt][2], c[mt][nt][3]);
        }
    }
}

// ---------------------------------------------------------------------------
// RK4 epilogue: kv = sum of 8 partials + b2; apply stage update.
// mode: 0 k1 / 1 k2 / 2 k3 / 3 k4 / 4 k4-final(write d_out)
__global__ __launch_bounds__(256) void rk4_epi(
    const float* __restrict__ b2, float dt, int mode, float* __restrict__ yout)
{
    const int i4 = blockIdx.x * blockDim.x + threadIdx.x;   // 0..131071
    const int i  = i4 * 4;
    const int col = i & (D_ - 1);

    float kv[4] = {0.f, 0.f, 0.f, 0.f};
#pragma unroll
    for (int z = 0; z < 8; z++) {
        float4 p = *reinterpret_cast<const float4*>(&g_part[z][i]);
        kv[0] += p.x; kv[1] += p.y; kv[2] += p.z; kv[3] += p.w;
    }
    float4 bb = *reinterpret_cast<const float4*>(&b2[col]);
    kv[0] += bb.x; kv[1] += bb.y; kv[2] += bb.z; kv[3] += bb.w;

    const float half_dt  = 0.5f * dt;
    const float sixth_dt = dt * (1.0f / 6.0f);

    float4 y = *reinterpret_cast<const float4*>(&g_y[i]);
    float yv[4] = {y.x, y.y, y.z, y.w};

    if (mode == 0) {
        float4 ac, yt;
        ac.x = kv[0]; ac.y = kv[1]; ac.z = kv[2]; ac.w = kv[3];
        yt.x = rna_tf32(yv[0] + half_dt * kv[0]);
        yt.y = rna_tf32(yv[1] + half_dt * kv[1]);
        yt.z = rna_tf32(yv[2] + half_dt * kv[2]);
        yt.w = rna_tf32(yv[3] + half_dt * kv[3]);
        *reinterpret_cast<float4*>(&g_acc[i])  = ac;
        *reinterpret_cast<float4*>(&g_ytmp[i]) = yt;
    } else if (mode == 1 || mode == 2) {
        float4 ac = *reinterpret_cast<const float4*>(&g_acc[i]);
        ac.x += 2.f * kv[0]; ac.y += 2.f * kv[1];
        ac.z += 2.f * kv[2]; ac.w += 2.f * kv[3];
        float step = (mode == 1) ? half_dt : dt;
        float4 yt;
        yt.x = rna_tf32(yv[0] + step * kv[0]);
        yt.y = rna_tf32(yv[1] + step * kv[1]);
        yt.z = rna_tf32(yv[2] + step * kv[2]);
        yt.w = rna_tf32(yv[3] + step * kv[3]);
        *reinterpret_cast<float4*>(&g_acc[i])  = ac;
        *reinterpret_cast<float4*>(&g_ytmp[i]) = yt;
    } else if (mode == 3) {
        float4 ac = *reinterpret_cast<const float4*>(&g_acc[i]);
        float4 yn, yr;
        yn.x = yv[0] + sixth_dt * (ac.x + kv[0]);
        yn.y = yv[1] + sixth_dt * (ac.y + kv[1]);
        yn.z = yv[2] + sixth_dt * (ac.z + kv[2]);
        yn.w = yv[3] + sixth_dt * (ac.w + kv[3]);
        yr.x = rna_tf32(yn.x); yr.y = rna_tf32(yn.y);
        yr.z = rna_tf32(yn.z); yr.w = rna_tf32(yn.w);
        *reinterpret_cast<float4*>(&g_y[i])  = yn;
        *reinterpret_cast<float4*>(&g_yr[i]) = yr;
    } else {
        float4 ac = *reinterpret_cast<const float4*>(&g_acc[i]);
        float4 o;
        o.x = yv[0] + sixth_dt * (ac.x + kv[0]);
        o.y = yv[1] + sixth_dt * (ac.y + kv[1]);
        o.z = yv[2] + sixth_dt * (ac.z + kv[2]);
        o.w = yv[3] + sixth_dt * (ac.w + kv[3]);
        *reinterpret_cast<float4*>(&yout[i]) = o;
    }
}

// ---------------------------------------------------------------------------
extern "C" void kernel_launch(void* const* d_in, const int* in_sizes, int n_in,
                              void* d_out, int out_size)
{
    const float* x  = (const float*)d_in[0];   // [1024, 512]
    const float* W1 = (const float*)d_in[1];   // [512, 2048]
    const float* b1 = (const float*)d_in[2];   // [2048]
    const float* W2 = (const float*)d_in[3];   // [2048, 512]
    const float* b2 = (const float*)d_in[4];   // [512]
    float* out = (float*)d_out;                // [1024, 512]

    const float dt = 1.0f / (float)NSTEPS;

    const int SMEM_G = (3 * ASLAB + 3 * BSLAB) * 4;   // 56,832 B
    cudaFuncSetAttribute(gemm1_tanh,   cudaFuncAttributeMaxDynamicSharedMemorySize, SMEM_G);
    cudaFuncSetAttribute(gemm2_splitk, cudaFuncAttributeMaxDynamicSharedMemorySize, SMEM_G);

    init_y_kernel<<<(B_ * D_ + 255) / 256, 256>>>(x);
    prep_weights_kernel<<<(D_ * H_ + 255) / 256, 256>>>(W1, W2);

    dim3 grid1(H_ / 128, B_ / 128);        // (16,8)  = 128 CTAs
    dim3 grid2(D_ / 128, B_ / 128, 8);     // (4,8,8) = 256 CTAs
    dim3 gridE((B_ * D_ / 4) / 256);       // 512 blocks

    for (int s = 0; s < NSTEPS; s++) {
        float t = dt * (float)s;

        gemm1_tanh  <<<grid1, 256, SMEM_G>>>(b1, t, /*in_sel=*/0);
        gemm2_splitk<<<grid2, 256, SMEM_G>>>();
        rk4_epi     <<<gridE, 256>>>(b2, dt, /*mode=*/0, out);

        gemm1_tanh  <<<grid1, 256, SMEM_G>>>(b1, t + 0.5f * dt, /*in_sel=*/1);
        gemm2_splitk<<<grid2, 256, SMEM_G>>>();
        rk4_epi     <<<gridE, 256>>>(b2, dt, /*mode=*/1, out);

        gemm1_tanh  <<<grid1, 256, SMEM_G>>>(b1, t + 0.5f * dt, /*in_sel=*/1);
        gemm2_splitk<<<grid2, 256, SMEM_G>>>();
        rk4_epi     <<<gridE, 256>>>(b2, dt, /*mode=*/2, out);

        gemm1_tanh  <<<grid1, 256, SMEM_G>>>(b1, t + dt, /*in_sel=*/1);
        gemm2_splitk<<<grid2, 256, SMEM_G>>>();
        int mode = (s == NSTEPS - 1) ? 4 : 3;
        rk4_epi     <<<gridE, 256>>>(b2, dt, mode, out);
    }
}

// round 15
// speedup vs baseline: 1.4588x; 1.0945x over previous
#include <cuda_runtime.h>
#include <math.h>

// Problem dims (fixed by the reference)
#define B_  1024
#define D_  512
#define H_  2048
#define NSTEPS 16

// ============================================================================
// Packed fragment layouts (all MMA operands pre-packed by their producers):
//
// A-pack (activations, [M x K] logical):
//   tile = m>>4, k8 = k>>3, lane = (m&7)*4 + (k&3),
//   slot = ((m>>3)&1) + 2*((k>>2)&1)
//   off  = ((tile*K8 + k8)*32 + lane)*4 + slot      (K8 = K/8)
//   -> one 16B chunk per (tile,k8,lane) = exactly one thread's m16n8k8 A frag.
//
// B-pack (weights, [K x N] logical, col-frag):
//   ntile = n>>5, nt = (n>>3)&3, k8 = k>>3, lane = (n&7)*4 + (k&3),
//   kh = (k>>2)&1
//   off = (((ntile*K8 + k8)*4 + nt)*32 + lane)*2 + kh
//   -> one 8B chunk per (ntile,k8,nt,lane) = one thread's B frag.
// ============================================================================

// -------- device scratch (allocation-free: static __device__ globals) ------
__device__ float g_y   [B_ * D_];      // state y, row-major (exact fp32)
__device__ float g_yr  [B_ * D_];      // A-pack of rna(y), K=512
__device__ float g_ytmp[B_ * D_];      // A-pack of rna(y + c*k), K=512
__device__ float g_acc [B_ * D_];      // RK4 accumulator, row-major
__device__ float g_h   [B_ * H_];      // A-pack of rna(tanh(...)), K=2048
__device__ float g_W1p [D_ * H_];      // B-pack of rna(W1), K=512, N=2048
__device__ float g_W2p [H_ * D_];      // B-pack of rna(W2), K=2048, N=512
__device__ float g_part[8][B_ * D_];   // split-K partials, row-major

// ---------------------------------------------------------------------------
__device__ __forceinline__ float rna_tf32(float x) {
    unsigned r;
    asm("cvt.rna.tf32.f32 %0, %1;" : "=r"(r) : "f"(x));
    return __uint_as_float(r);
}
__device__ __forceinline__ float fast_tanh(float x) {
    float y;
    asm("tanh.approx.f32 %0, %1;" : "=f"(y) : "f"(x));
    return y;
}
// mma.sync m16n8k8 tf32: D = A@B + C, fp32 accumulate. Inputs tf32-exact.
__device__ __forceinline__ void mma_tf32(float* c, const unsigned* a, const unsigned* b) {
    asm volatile(
        "mma.sync.aligned.m16n8k8.row.col.f32.tf32.tf32.f32 "
        "{%0,%1,%2,%3}, {%4,%5,%6,%7}, {%8,%9}, {%0,%1,%2,%3};"
        : "+f"(c[0]), "+f"(c[1]), "+f"(c[2]), "+f"(c[3])
        : "r"(a[0]), "r"(a[1]), "r"(a[2]), "r"(a[3]),
          "r"(b[0]), "r"(b[1]));
}
__device__ __forceinline__ void cp_async16(float* smem_dst, const float* gmem_src) {
    unsigned s = (unsigned)__cvta_generic_to_shared(smem_dst);
    asm volatile("cp.async.ca.shared.global [%0], [%1], 16;\n" :: "r"(s), "l"(gmem_src));
}
__device__ __forceinline__ void cp_commit() {
    asm volatile("cp.async.commit_group;\n");
}
template <int N>
__device__ __forceinline__ void cp_wait() {
    asm volatile("cp.async.wait_group %0;\n" :: "n"(N));
}

// ---------------------------------------------------------------------------
// A-pack offset helpers
__device__ __forceinline__ int apack_off(int m, int k, int K8) {
    int tile = m >> 4, k8 = k >> 3;
    int lane = (m & 7) * 4 + (k & 3);
    int slot = ((m >> 3) & 1) + 2 * ((k >> 2) & 1);
    return ((tile * K8 + k8) * 32 + lane) * 4 + slot;
}
__device__ __forceinline__ int bpack_off(int k, int n, int K8) {
    int ntile = n >> 5, nt = (n >> 3) & 3, k8 = k >> 3;
    int lane = (n & 7) * 4 + (k & 3);
    int kh = (k >> 2) & 1;
    return (((ntile * K8 + k8) * 4 + nt) * 32 + lane) * 2 + kh;
}

// ---------------------------------------------------------------------------
__global__ void init_y_kernel(const float* __restrict__ x) {
    int i = blockIdx.x * blockDim.x + threadIdx.x;
    if (i < B_ * D_) {
        float v = x[i];
        g_y[i] = v;
        int m = i >> 9, k = i & 511;
        g_yr[apack_off(m, k, 64)] = rna_tf32(v);
    }
}
__global__ void prep_weights_kernel(const float* __restrict__ W1,
                                    const float* __restrict__ W2) {
    int i = blockIdx.x * blockDim.x + threadIdx.x;
    if (i < D_ * H_) {
        // W1: [512, 2048] row-major -> B-pack K8=64
        int k1 = i >> 11, n1 = i & 2047;
        g_W1p[bpack_off(k1, n1, 64)] = rna_tf32(W1[i]);
        // W2: [2048, 512] row-major -> B-pack K8=256
        int k2 = i >> 9, n2 = i & 511;
        g_W2p[bpack_off(k2, n2, 256)] = rna_tf32(W2[i]);
    }
}

// ---------------------------------------------------------------------------
// SMEM (floats), dynamic 49,152 B per CTA, both GEMMs:
//   Sa(s) at s*2048  (A slab 8KB, packed chunk order)
//   Sb(s) at 6144 + s*2048 (B slab 8KB, packed chunk order)
#define SB0 6144

// ---------------------------------------------------------------------------
// GEMM1:  g_h = A-pack( rna( tanh( Ain @ W1 + b1 + t ) ) )
//   CTA 128x128, BK=16, 256 threads = 8 warps (2M x 4N), warp tile 64x32.
//   Frag loads: 4x LDS.128 (A) + 4x LDS.64 (B) per k8 (was 24x LDS.32).
//   Grid (16,8) = 128 CTAs.
__global__ __launch_bounds__(256) void gemm1_tanh(
    const float* __restrict__ b1, float t, int in_sel)
{
    extern __shared__ float S[];

    const float* __restrict__ Ain = in_sel ? g_ytmp : g_yr;  // A-pack K8=64
    const float* __restrict__ Bw  = g_W1p;                    // B-pack K8=64

    const int tid  = threadIdx.x;
    const int lane = tid & 31;
    const int warp = tid >> 5;
    const int g    = lane >> 2;
    const int t4   = lane & 3;
    const int wm   = warp & 1;      // m offset wm*64
    const int wn   = warp >> 1;     // n offset wn*32

    const int tile0  = blockIdx.y * 8;   // 128 rows = 8 m-tiles
    const int ntile0 = blockIdx.x * 4;   // 128 cols = 4 n-tiles
    const int bn0    = blockIdx.x * 128;
    const int bm0    = blockIdx.y * 128;

    auto load_slab = [&](int k0, int s) {
        const int k8b = k0 >> 3;
        // A: 512 chunks (8 tiles x 2 k8 x 32 lanes), 2/thread
#pragma unroll
        for (int i = 0; i < 2; i++) {
            int id = tid + 256 * i;
            int tl = id >> 6, k8L = (id >> 5) & 1, ln = id & 31;
            cp_async16(&S[s * 2048 + id * 4],
                       &Ain[(((tile0 + tl) * 64 + k8b + k8L) * 32 + ln) * 4]);
        }
        // B: 512 chunks (4 ntiles x 2 k8 x 4 nt x 16 lane-pairs), 2/thread
#pragma unroll
        for (int i = 0; i < 2; i++) {
            int id = tid + 256 * i;
            int ntl = id >> 7, k8L = (id >> 6) & 1, nt = (id >> 4) & 3, ln = (id & 15) * 2;
            cp_async16(&S[SB0 + s * 2048 + id * 4],
                       &Bw[((((ntile0 + ntl) * 64 + k8b + k8L) * 4 + nt) * 32 + ln) * 2]);
        }
        cp_commit();
    };

    float c[4][4][4];
#pragma unroll
    for (int i = 0; i < 4; i++)
#pragma unroll
        for (int j = 0; j < 4; j++)
#pragma unroll
            for (int e = 0; e < 4; e++) c[i][j][e] = 0.f;

    const int NS = D_ / 16;   // 32 slabs
    load_slab(0, 0);
    load_slab(16, 1);

    for (int si = 0; si < NS; si++) {
        if (si + 1 < NS) cp_wait<1>(); else cp_wait<0>();
        __syncthreads();
        if (si + 2 < NS) load_slab((si + 2) * 16, (si + 2) % 3);

        const float* Sa = &S[(si % 3) * 2048];
        const float* Sb = &S[SB0 + (si % 3) * 2048];
#pragma unroll
        for (int k8L = 0; k8L < 2; k8L++) {
            unsigned a[4][4], b[4][2];
#pragma unroll
            for (int mt = 0; mt < 4; mt++) {
                int tile = wm * 4 + mt;
                uint4 av = *reinterpret_cast<const uint4*>(
                    &Sa[((tile * 2 + k8L) * 32 + lane) * 4]);
                a[mt][0] = av.x; a[mt][1] = av.y; a[mt][2] = av.z; a[mt][3] = av.w;
            }
#pragma unroll
            for (int nt = 0; nt < 4; nt++) {
                uint2 bv = *reinterpret_cast<const uint2*>(
                    &Sb[(((wn * 2 + k8L) * 4 + nt) * 32 + lane) * 2]);
                b[nt][0] = bv.x; b[nt][1] = bv.y;
            }
#pragma unroll
            for (int mt = 0; mt < 4; mt++)
#pragma unroll
                for (int nt = 0; nt < 4; nt++)
                    mma_tf32(c[mt][nt], a[mt], b[nt]);
        }
    }

    // epilogue: rna(tanh(c + b1 + t)) -> g_h in A-pack layout (K8=256)
#pragma unroll
    for (int mt = 0; mt < 4; mt++) {
        int row0 = bm0 + wm * 64 + mt * 16 + g;   // g<8 -> half0; +8 -> half1
        int tile = row0 >> 4;
#pragma unroll
        for (int nt = 0; nt < 4; nt++) {
            int col0 = bn0 + wn * 32 + nt * 8 + 2 * t4;
            int k8   = col0 >> 3;
            int kh   = (col0 >> 2) & 1;
            int ln0  = g * 4 + (col0 & 3);
            int base = ((tile * 256 + k8) * 32) * 4 + 2 * kh;
            float bb0 = b1[col0] + t, bb1 = b1[col0 + 1] + t;
            g_h[base + ln0 * 4 + 0]       = rna_tf32(fast_tanh(c[mt][nt][0] + bb0));
            g_h[base + (ln0 + 1) * 4 + 0] = rna_tf32(fast_tanh(c[mt][nt][1] + bb1));
            g_h[base + ln0 * 4 + 1]       = rna_tf32(fast_tanh(c[mt][nt][2] + bb0));
            g_h[base + (ln0 + 1) * 4 + 1] = rna_tf32(fast_tanh(c[mt][nt][3] + bb1));
        }
    }
}

// ---------------------------------------------------------------------------
// GEMM2 split-K x8:
//   partial[z] = g_h[:, z*256:(z+1)*256] @ W2[z*256:(z+1)*256, :]
//   CTA 128x128, K-slice 256, BK=16, 256 threads, warp tile 64x32.
//   Grid (4,8,8) = 256 CTAs. Same vectorized frag loads.
__global__ __launch_bounds__(256) void gemm2_splitk()
{
    extern __shared__ float S[];

    const int tid  = threadIdx.x;
    const int lane = tid & 31;
    const int warp = tid >> 5;
    const int g    = lane >> 2;
    const int t4   = lane & 3;
    const int wm   = warp & 1;
    const int wn   = warp >> 1;

    const int tile0  = blockIdx.y * 8;
    const int ntile0 = blockIdx.x * 4;
    const int bn0    = blockIdx.x * 128;
    const int bm0    = blockIdx.y * 128;
    const int k8z    = blockIdx.z * 32;   // K-slice base in k8 units (256/8)

    auto load_slab = [&](int k0, int s) {
        const int k8b = k8z + (k0 >> 3);
#pragma unroll
        for (int i = 0; i < 2; i++) {
            int id = tid + 256 * i;
            int tl = id >> 6, k8L = (id >> 5) & 1, ln = id & 31;
            cp_async16(&S[s * 2048 + id * 4],
                       &g_h[(((tile0 + tl) * 256 + k8b + k8L) * 32 + ln) * 4]);
        }
#pragma unroll
        for (int i = 0; i < 2; i++) {
            int id = tid + 256 * i;
            int ntl = id >> 7, k8L = (id >> 6) & 1, nt = (id >> 4) & 3, ln = (id & 15) * 2;
            cp_async16(&S[SB0 + s * 2048 + id * 4],
                       &g_W2p[((((ntile0 + ntl) * 256 + k8b + k8L) * 4 + nt) * 32 + ln) * 2]);
        }
        cp_commit();
    };

    float c[4][4][4];
#pragma unroll
    for (int i = 0; i < 4; i++)
#pragma unroll
        for (int j = 0; j < 4; j++)
#pragma unroll
            for (int e = 0; e < 4; e++) c[i][j][e] = 0.f;

    const int NS = 256 / 16;   // 16 slabs
    load_slab(0, 0);
    load_slab(16, 1);

    for (int si = 0; si < NS; si++) {
        if (si + 1 < NS) cp_wait<1>(); else cp_wait<0>();
        __syncthreads();
        if (si + 2 < NS) load_slab((si + 2) * 16, (si + 2) % 3);

        const float* Sa = &S[(si % 3) * 2048];
        const float* Sb = &S[SB0 + (si % 3) * 2048];
#pragma unroll
        for (int k8L = 0; k8L < 2; k8L++) {
            unsigned a[4][4], b[4][2];
#pragma unroll
            for (int mt = 0; mt < 4; mt++) {
                int tile = wm * 4 + mt;
                uint4 av = *reinterpret_cast<const uint4*>(
                    &Sa[((tile * 2 + k8L) * 32 + lane) * 4]);
                a[mt][0] = av.x; a[mt][1] = av.y; a[mt][2] = av.z; a[mt][3] = av.w;
            }
#pragma unroll
            for (int nt = 0; nt < 4; nt++) {
                uint2 bv = *reinterpret_cast<const uint2*>(
                    &Sb[(((wn * 2 + k8L) * 4 + nt) * 32 + lane) * 2]);
                b[nt][0] = bv.x; b[nt][1] = bv.y;
            }
#pragma unroll
            for (int mt = 0; mt < 4; mt++)
#pragma unroll
                for (int nt = 0; nt < 4; nt++)
                    mma_tf32(c[mt][nt], a[mt], b[nt]);
        }
    }

    // write raw partial tile (row-major, as before)
    float* __restrict__ P = g_part[blockIdx.z];
#pragma unroll
    for (int mt = 0; mt < 4; mt++) {
        int row0 = bm0 + wm * 64 + mt * 16 + g;
#pragma unroll
        for (int nt = 0; nt < 4; nt++) {
            int col = bn0 + wn * 32 + nt * 8 + 2 * t4;
            *reinterpret_cast<float2*>(&P[(size_t)row0 * D_ + col]) =
                make_float2(c[mt][nt][0], c[mt][nt][1]);
            *reinterpret_cast<float2*>(&P[(size_t)(row0 + 8) * D_ + col]) =
                make_float2(c[mt][nt][2], c[mt][nt][3]);
        }
    }
}

// ---------------------------------------------------------------------------
// RK4 epilogue: kv = sum of 8 partials + b2; apply stage update.
// g_ytmp/g_yr written in A-pack layout (K8=64).
// mode: 0 k1 / 1 k2 / 2 k3 / 3 k4 / 4 k4-final(write d_out)
__global__ __launch_bounds__(256) void rk4_epi(
    const float* __restrict__ b2, float dt, int mode, float* __restrict__ yout)
{
    const int i4 = blockIdx.x * blockDim.x + threadIdx.x;   // 0..131071
    const int i  = i4 * 4;
    const int m   = i >> 9;
    const int k   = i & 511;          // k % 4 == 0
    const int col = k;

    float kv[4] = {0.f, 0.f, 0.f, 0.f};
#pragma unroll
    for (int z = 0; z < 8; z++) {
        float4 p = *reinterpret_cast<const float4*>(&g_part[z][i]);
        kv[0] += p.x; kv[1] += p.y; kv[2] += p.z; kv[3] += p.w;
    }
    float4 bb = *reinterpret_cast<const float4*>(&b2[col]);
    kv[0] += bb.x; kv[1] += bb.y; kv[2] += bb.z; kv[3] += bb.w;

    const float half_dt  = 0.5f * dt;
    const float sixth_dt = dt * (1.0f / 6.0f);

    float4 y = *reinterpret_cast<const float4*>(&g_y[i]);
    float yv[4] = {y.x, y.y, y.z, y.w};

    // A-pack base for (m, k..k+3): lane = (m&7)*4 + j, slot fixed
    const int pbase = (((m >> 4) * 64 + (k >> 3)) * 32 + (m & 7) * 4) * 4
                      + ((m >> 3) & 1) + 2 * ((k >> 2) & 1);

    if (mode == 0) {
        float4 ac;
        ac.x = kv[0]; ac.y = kv[1]; ac.z = kv[2]; ac.w = kv[3];
        *reinterpret_cast<float4*>(&g_acc[i]) = ac;
#pragma unroll
        for (int j = 0; j < 4; j++)
            g_ytmp[pbase + j * 4] = rna_tf32(yv[j] + half_dt * kv[j]);
    } else if (mode == 1 || mode == 2) {
        float4 ac = *reinterpret_cast<const float4*>(&g_acc[i]);
        ac.x += 2.f * kv[0]; ac.y += 2.f * kv[1];
        ac.z += 2.f * kv[2]; ac.w += 2.f * kv[3];
        *reinterpret_cast<float4*>(&g_acc[i]) = ac;
        float step = (mode == 1) ? half_dt : dt;
#pragma unroll
        for (int j = 0; j < 4; j++)
            g_ytmp[pbase + j * 4] = rna_tf32(yv[j] + step * kv[j]);
    } else if (mode == 3) {
        float4 ac = *reinterpret_cast<const float4*>(&g_acc[i]);
        float acv[4] = {ac.x, ac.y, ac.z, ac.w};
        float4 yn;
        yn.x = yv[0] + sixth_dt * (acv[0] + kv[0]);
        yn.y = yv[1] + sixth_dt * (acv[1] + kv[1]);
        yn.z = yv[2] + sixth_dt * (acv[2] + kv[2]);
        yn.w = yv[3] + sixth_dt * (acv[3] + kv[3]);
        *reinterpret_cast<float4*>(&g_y[i]) = yn;
        float ynv[4] = {yn.x, yn.y, yn.z, yn.w};
#pragma unroll
        for (int j = 0; j < 4; j++)
            g_yr[pbase + j * 4] = rna_tf32(ynv[j]);
    } else {
        float4 ac = *reinterpret_cast<const float4*>(&g_acc[i]);
        float4 o;
        o.x = yv[0] + sixth_dt * (ac.x + kv[0]);
        o.y = yv[1] + sixth_dt * (ac.y + kv[1]);
        o.z = yv[2] + sixth_dt * (ac.z + kv[2]);
        o.w = yv[3] + sixth_dt * (ac.w + kv[3]);
        *reinterpret_cast<float4*>(&yout[i]) = o;
    }
}

// ---------------------------------------------------------------------------
extern "C" void kernel_launch(void* const* d_in, const int* in_sizes, int n_in,
                              void* d_out, int out_size)
{
    const float* x  = (const float*)d_in[0];   // [1024, 512]
    const float* W1 = (const float*)d_in[1];   // [512, 2048]
    const float* b1 = (const float*)d_in[2];   // [2048]
    const float* W2 = (const float*)d_in[3];   // [2048, 512]
    const float* b2 = (const float*)d_in[4];   // [512]
    float* out = (float*)d_out;                // [1024, 512]

    const float dt = 1.0f / (float)NSTEPS;

    const int SMEM_G = 12288 * 4;   // 49,152 B (3 x (8KB A + 8KB B))
    cudaFuncSetAttribute(gemm1_tanh,   cudaFuncAttributeMaxDynamicSharedMemorySize, SMEM_G);
    cudaFuncSetAttribute(gemm2_splitk, cudaFuncAttributeMaxDynamicSharedMemorySize, SMEM_G);

    init_y_kernel<<<(B_ * D_ + 255) / 256, 256>>>(x);
    prep_weights_kernel<<<(D_ * H_ + 255) / 256, 256>>>(W1, W2);

    dim3 grid1(H_ / 128, B_ / 128);        // (16,8)  = 128 CTAs
    dim3 grid2(D_ / 128, B_ / 128, 8);     // (4,8,8) = 256 CTAs
    dim3 gridE((B_ * D_ / 4) / 256);       // 512 blocks

    for (int s = 0; s < NSTEPS; s++) {
        float t = dt * (float)s;

        gemm1_tanh  <<<grid1, 256, SMEM_G>>>(b1, t, /*in_sel=*/0);
        gemm2_splitk<<<grid2, 256, SMEM_G>>>();
        rk4_epi     <<<gridE, 256>>>(b2, dt, /*mode=*/0, out);

        gemm1_tanh  <<<grid1, 256, SMEM_G>>>(b1, t + 0.5f * dt, /*in_sel=*/1);
        gemm2_splitk<<<grid2, 256, SMEM_G>>>();
        rk4_epi     <<<gridE, 256>>>(b2, dt, /*mode=*/1, out);

        gemm1_tanh  <<<grid1, 256, SMEM_G>>>(b1, t + 0.5f * dt, /*in_sel=*/1);
        gemm2_splitk<<<grid2, 256, SMEM_G>>>();
        rk4_epi     <<<gridE, 256>>>(b2, dt, /*mode=*/2, out);

        gemm1_tanh  <<<grid1, 256, SMEM_G>>>(b1, t + dt, /*in_sel=*/1);
        gemm2_splitk<<<grid2, 256, SMEM_G>>>();
        int mode = (s == NSTEPS - 1) ? 4 : 3;
        rk4_epi     <<<gridE, 256>>>(b2, dt, mode, out);
    }
}

// round 16
// speedup vs baseline: 1.5193x; 1.0415x over previous
#include <cuda_runtime.h>
#include <math.h>

// Problem dims (fixed by the reference)
#define B_  1024
#define D_  512
#define H_  2048
#define NSTEPS 16

// ============================================================================
// Packed fragment layouts (all MMA operands pre-packed by their producers):
//
// A-pack (activations, [M x K] logical):
//   tile = m>>4, k8 = k>>3, lane = (m&7)*4 + (k&3),
//   slot = ((m>>3)&1) + 2*((k>>2)&1)
//   off  = ((tile*K8 + k8)*32 + lane)*4 + slot      (K8 = K/8)
//   -> one 16B chunk per (tile,k8,lane) = exactly one thread's m16n8k8 A frag.
//
// B-pack (weights, [K x N] logical, col-frag):
//   ntile = n>>5, nt = (n>>3)&3, k8 = k>>3, lane = (n&7)*4 + (k&3),
//   kh = (k>>2)&1
//   off = (((ntile*K8 + k8)*4 + nt)*32 + lane)*2 + kh
//   -> one 8B chunk per (ntile,k8,nt,lane) = one thread's B frag.
// ============================================================================

// -------- device scratch (allocation-free: static __device__ globals) ------
__device__ float g_y   [B_ * D_];      // state y, row-major (exact fp32)
__device__ float g_yr  [B_ * D_];      // A-pack of rna(y), K=512
__device__ float g_ytmp[B_ * D_];      // A-pack of rna(y + c*k), K=512
__device__ float g_acc [B_ * D_];      // RK4 accumulator, row-major
__device__ float g_h   [B_ * H_];      // A-pack of rna(tanh(...)), K=2048
__device__ float g_W1p [D_ * H_];      // B-pack of rna(W1), K=512, N=2048
__device__ float g_W2p [H_ * D_];      // B-pack of rna(W2), K=2048, N=512
__device__ float g_part[8][B_ * D_];   // split-K partials, row-major

// ---------------------------------------------------------------------------
__device__ __forceinline__ float rna_tf32(float x) {
    unsigned r;
    asm("cvt.rna.tf32.f32 %0, %1;" : "=r"(r) : "f"(x));
    return __uint_as_float(r);
}
__device__ __forceinline__ float fast_tanh(float x) {
    float y;
    asm("tanh.approx.f32 %0, %1;" : "=f"(y) : "f"(x));
    return y;
}
// mma.sync m16n8k8 tf32: D = A@B + C, fp32 accumulate. Inputs tf32-exact.
__device__ __forceinline__ void mma_tf32(float* c, const unsigned* a, const unsigned* b) {
    asm volatile(
        "mma.sync.aligned.m16n8k8.row.col.f32.tf32.tf32.f32 "
        "{%0,%1,%2,%3}, {%4,%5,%6,%7}, {%8,%9}, {%0,%1,%2,%3};"
        : "+f"(c[0]), "+f"(c[1]), "+f"(c[2]), "+f"(c[3])
        : "r"(a[0]), "r"(a[1]), "r"(a[2]), "r"(a[3]),
          "r"(b[0]), "r"(b[1]));
}
__device__ __forceinline__ void cp_async16(float* smem_dst, const float* gmem_src) {
    unsigned s = (unsigned)__cvta_generic_to_shared(smem_dst);
    asm volatile("cp.async.ca.shared.global [%0], [%1], 16;\n" :: "r"(s), "l"(gmem_src));
}
__device__ __forceinline__ void cp_commit() {
    asm volatile("cp.async.commit_group;\n");
}
template <int N>
__device__ __forceinline__ void cp_wait() {
    asm volatile("cp.async.wait_group %0;\n" :: "n"(N));
}

// ---------------------------------------------------------------------------
__device__ __forceinline__ int apack_off(int m, int k, int K8) {
    int tile = m >> 4, k8 = k >> 3;
    int lane = (m & 7) * 4 + (k & 3);
    int slot = ((m >> 3) & 1) + 2 * ((k >> 2) & 1);
    return ((tile * K8 + k8) * 32 + lane) * 4 + slot;
}
__device__ __forceinline__ int bpack_off(int k, int n, int K8) {
    int ntile = n >> 5, nt = (n >> 3) & 3, k8 = k >> 3;
    int lane = (n & 7) * 4 + (k & 3);
    int kh = (k >> 2) & 1;
    return (((ntile * K8 + k8) * 4 + nt) * 32 + lane) * 2 + kh;
}

// ---------------------------------------------------------------------------
__global__ void init_y_kernel(const float* __restrict__ x) {
    int i = blockIdx.x * blockDim.x + threadIdx.x;
    if (i < B_ * D_) {
        float v = x[i];
        g_y[i] = v;
        int m = i >> 9, k = i & 511;
        g_yr[apack_off(m, k, 64)] = rna_tf32(v);
    }
}
__global__ void prep_weights_kernel(const float* __restrict__ W1,
                                    const float* __restrict__ W2) {
    int i = blockIdx.x * blockDim.x + threadIdx.x;
    if (i < D_ * H_) {
        int k1 = i >> 11, n1 = i & 2047;
        g_W1p[bpack_off(k1, n1, 64)] = rna_tf32(W1[i]);
        int k2 = i >> 9, n2 = i & 511;
        g_W2p[bpack_off(k2, n2, 256)] = rna_tf32(W2[i]);
    }
}

// ---------------------------------------------------------------------------
// SMEM (floats), dynamic 98,304 B per CTA, BK=32, both GEMMs:
//   Sa(s) at s*4096          (A slab 16KB: [8 tiles][4 k8][32 lanes] x 16B)
//   Sb(s) at 12288 + s*4096  (B slab 16KB: [4 ntl][4 k8][4 nt][32 lanes] x 8B)
//   2 CTAs/SM x 96KB = 192KB <= 228KB.
#define SB0 12288

// ---------------------------------------------------------------------------
// GEMM1:  g_h = A-pack( rna( tanh( Ain @ W1 + b1 + t ) ) )
//   CTA 128x128, BK=32, 256 threads = 8 warps (2M x 4N), warp tile 64x32.
//   16 slabs, 16 syncs (was 32). Grid (16,8) = 128 CTAs.
__global__ __launch_bounds__(256) void gemm1_tanh(
    const float* __restrict__ b1, float t, int in_sel)
{
    extern __shared__ float S[];

    const float* __restrict__ Ain = in_sel ? g_ytmp : g_yr;  // A-pack K8=64
    const float* __restrict__ Bw  = g_W1p;                    // B-pack K8=64

    const int tid  = threadIdx.x;
    const int lane = tid & 31;
    const int warp = tid >> 5;
    const int g    = lane >> 2;
    const int t4   = lane & 3;
    const int wm   = warp & 1;      // m offset wm*64
    const int wn   = warp >> 1;     // n offset wn*32

    const int tile0  = blockIdx.y * 8;
    const int ntile0 = blockIdx.x * 4;
    const int bn0    = blockIdx.x * 128;
    const int bm0    = blockIdx.y * 128;

    auto load_slab = [&](int k0, int s) {
        const int k8b = k0 >> 3;
        // A: 1024 chunks (8 tiles x 4 k8 x 32 lanes), 4/thread
#pragma unroll
        for (int i = 0; i < 4; i++) {
            int id = tid + 256 * i;
            int tl = id >> 7, k8L = (id >> 5) & 3, ln = id & 31;
            cp_async16(&S[s * 4096 + id * 4],
                       &Ain[(((tile0 + tl) * 64 + k8b + k8L) * 32 + ln) * 4]);
        }
        // B: 1024 chunks (4 ntl x 4 k8 x 4 nt x 16 lane-pairs), 4/thread
#pragma unroll
        for (int i = 0; i < 4; i++) {
            int id = tid + 256 * i;
            int ntl = id >> 8, k8L = (id >> 6) & 3, nt = (id >> 4) & 3, ln = (id & 15) * 2;
            cp_async16(&S[SB0 + s * 4096 + id * 4],
                       &Bw[((((ntile0 + ntl) * 64 + k8b + k8L) * 4 + nt) * 32 + ln) * 2]);
        }
        cp_commit();
    };

    float c[4][4][4];
#pragma unroll
    for (int i = 0; i < 4; i++)
#pragma unroll
        for (int j = 0; j < 4; j++)
#pragma unroll
            for (int e = 0; e < 4; e++) c[i][j][e] = 0.f;

    const int NS = D_ / 32;   // 16 slabs
    load_slab(0, 0);
    load_slab(32, 1);

    for (int si = 0; si < NS; si++) {
        if (si + 1 < NS) cp_wait<1>(); else cp_wait<0>();
        __syncthreads();
        if (si + 2 < NS) load_slab((si + 2) * 32, (si + 2) % 3);

        const float* Sa = &S[(si % 3) * 4096];
        const float* Sb = &S[SB0 + (si % 3) * 4096];
#pragma unroll
        for (int k8L = 0; k8L < 4; k8L++) {
            unsigned a[4][4], b[4][2];
#pragma unroll
            for (int mt = 0; mt < 4; mt++) {
                int tile = wm * 4 + mt;
                uint4 av = *reinterpret_cast<const uint4*>(
                    &Sa[((tile * 4 + k8L) * 32 + lane) * 4]);
                a[mt][0] = av.x; a[mt][1] = av.y; a[mt][2] = av.z; a[mt][3] = av.w;
            }
#pragma unroll
            for (int nt = 0; nt < 4; nt++) {
                uint2 bv = *reinterpret_cast<const uint2*>(
                    &Sb[(((wn * 4 + k8L) * 4 + nt) * 32 + lane) * 2]);
                b[nt][0] = bv.x; b[nt][1] = bv.y;
            }
#pragma unroll
            for (int mt = 0; mt < 4; mt++)
#pragma unroll
                for (int nt = 0; nt < 4; nt++)
                    mma_tf32(c[mt][nt], a[mt], b[nt]);
        }
    }

    // epilogue: rna(tanh(c + b1 + t)) -> g_h in A-pack layout (K8=256)
#pragma unroll
    for (int mt = 0; mt < 4; mt++) {
        int row0 = bm0 + wm * 64 + mt * 16 + g;
        int tile = row0 >> 4;
#pragma unroll
        for (int nt = 0; nt < 4; nt++) {
            int col0 = bn0 + wn * 32 + nt * 8 + 2 * t4;
            int k8   = col0 >> 3;
            int kh   = (col0 >> 2) & 1;
            int ln0  = g * 4 + (col0 & 3);
            int base = ((tile * 256 + k8) * 32) * 4 + 2 * kh;
            float bb0 = b1[col0] + t, bb1 = b1[col0 + 1] + t;
            g_h[base + ln0 * 4 + 0]       = rna_tf32(fast_tanh(c[mt][nt][0] + bb0));
            g_h[base + (ln0 + 1) * 4 + 0] = rna_tf32(fast_tanh(c[mt][nt][1] + bb1));
            g_h[base + ln0 * 4 + 1]       = rna_tf32(fast_tanh(c[mt][nt][2] + bb0));
            g_h[base + (ln0 + 1) * 4 + 1] = rna_tf32(fast_tanh(c[mt][nt][3] + bb1));
        }
    }
}

// ---------------------------------------------------------------------------
// GEMM2 split-K x8:
//   partial[z] = g_h[:, z*256:(z+1)*256] @ W2[z*256:(z+1)*256, :]
//   CTA 128x128, K-slice 256, BK=32, 256 threads, warp tile 64x32.
//   8 slabs, 8 syncs (was 16). Grid (4,8,8) = 256 CTAs.
__global__ __launch_bounds__(256) void gemm2_splitk()
{
    extern __shared__ float S[];

    const int tid  = threadIdx.x;
    const int lane = tid & 31;
    const int warp = tid >> 5;
    const int g    = lane >> 2;
    const int t4   = lane & 3;
    const int wm   = warp & 1;
    const int wn   = warp >> 1;

    const int tile0  = blockIdx.y * 8;
    const int ntile0 = blockIdx.x * 4;
    const int bn0    = blockIdx.x * 128;
    const int bm0    = blockIdx.y * 128;
    const int k8z    = blockIdx.z * 32;   // K-slice base in k8 units

    auto load_slab = [&](int k0, int s) {
        const int k8b = k8z + (k0 >> 3);
#pragma unroll
        for (int i = 0; i < 4; i++) {
            int id = tid + 256 * i;
            int tl = id >> 7, k8L = (id >> 5) & 3, ln = id & 31;
            cp_async16(&S[s * 4096 + id * 4],
                       &g_h[(((tile0 + tl) * 256 + k8b + k8L) * 32 + ln) * 4]);
        }
#pragma unroll
        for (int i = 0; i < 4; i++) {
            int id = tid + 256 * i;
            int ntl = id >> 8, k8L = (id >> 6) & 3, nt = (id >> 4) & 3, ln = (id & 15) * 2;
            cp_async16(&S[SB0 + s * 4096 + id * 4],
                       &g_W2p[((((ntile0 + ntl) * 256 + k8b + k8L) * 4 + nt) * 32 + ln) * 2]);
        }
        cp_commit();
    };

    float c[4][4][4];
#pragma unroll
    for (int i = 0; i < 4; i++)
#pragma unroll
        for (int j = 0; j < 4; j++)
#pragma unroll
            for (int e = 0; e < 4; e++) c[i][j][e] = 0.f;

    const int NS = 256 / 32;   // 8 slabs
    load_slab(0, 0);
    load_slab(32, 1);

    for (int si = 0; si < NS; si++) {
        if (si + 1 < NS) cp_wait<1>(); else cp_wait<0>();
        __syncthreads();
        if (si + 2 < NS) load_slab((si + 2) * 32, (si + 2) % 3);

        const float* Sa = &S[(si % 3) * 4096];
        const float* Sb = &S[SB0 + (si % 3) * 4096];
#pragma unroll
        for (int k8L = 0; k8L < 4; k8L++) {
            unsigned a[4][4], b[4][2];
#pragma unroll
            for (int mt = 0; mt < 4; mt++) {
                int tile = wm * 4 + mt;
                uint4 av = *reinterpret_cast<const uint4*>(
                    &Sa[((tile * 4 + k8L) * 32 + lane) * 4]);
                a[mt][0] = av.x; a[mt][1] = av.y; a[mt][2] = av.z; a[mt][3] = av.w;
            }
#pragma unroll
            for (int nt = 0; nt < 4; nt++) {
                uint2 bv = *reinterpret_cast<const uint2*>(
                    &Sb[(((wn * 4 + k8L) * 4 + nt) * 32 + lane) * 2]);
                b[nt][0] = bv.x; b[nt][1] = bv.y;
            }
#pragma unroll
            for (int mt = 0; mt < 4; mt++)
#pragma unroll
                for (int nt = 0; nt < 4; nt++)
                    mma_tf32(c[mt][nt], a[mt], b[nt]);
        }
    }

    // write raw partial tile (row-major)
    float* __restrict__ P = g_part[blockIdx.z];
#pragma unroll
    for (int mt = 0; mt < 4; mt++) {
        int row0 = bm0 + wm * 64 + mt * 16 + g;
#pragma unroll
        for (int nt = 0; nt < 4; nt++) {
            int col = bn0 + wn * 32 + nt * 8 + 2 * t4;
            *reinterpret_cast<float2*>(&P[(size_t)row0 * D_ + col]) =
                make_float2(c[mt][nt][0], c[mt][nt][1]);
            *reinterpret_cast<float2*>(&P[(size_t)(row0 + 8) * D_ + col]) =
                make_float2(c[mt][nt][2], c[mt][nt][3]);
        }
    }
}

// ---------------------------------------------------------------------------
// RK4 epilogue: kv = sum of 8 partials + b2; apply stage update.
// g_ytmp/g_yr written in A-pack layout (K8=64).
// mode: 0 k1 / 1 k2 / 2 k3 / 3 k4 / 4 k4-final(write d_out)
__global__ __launch_bounds__(256) void rk4_epi(
    const float* __restrict__ b2, float dt, int mode, float* __restrict__ yout)
{
    const int i4 = blockIdx.x * blockDim.x + threadIdx.x;   // 0..131071
    const int i  = i4 * 4;
    const int m   = i >> 9;
    const int k   = i & 511;          // k % 4 == 0
    const int col = k;

    float kv[4] = {0.f, 0.f, 0.f, 0.f};
#pragma unroll
    for (int z = 0; z < 8; z++) {
        float4 p = *reinterpret_cast<const float4*>(&g_part[z][i]);
        kv[0] += p.x; kv[1] += p.y; kv[2] += p.z; kv[3] += p.w;
    }
    float4 bb = *reinterpret_cast<const float4*>(&b2[col]);
    kv[0] += bb.x; kv[1] += bb.y; kv[2] += bb.z; kv[3] += bb.w;

    const float half_dt  = 0.5f * dt;
    const float sixth_dt = dt * (1.0f / 6.0f);

    float4 y = *reinterpret_cast<const float4*>(&g_y[i]);
    float yv[4] = {y.x, y.y, y.z, y.w};

    const int pbase = (((m >> 4) * 64 + (k >> 3)) * 32 + (m & 7) * 4) * 4
                      + ((m >> 3) & 1) + 2 * ((k >> 2) & 1);

    if (mode == 0) {
        float4 ac;
        ac.x = kv[0]; ac.y = kv[1]; ac.z = kv[2]; ac.w = kv[3];
        *reinterpret_cast<float4*>(&g_acc[i]) = ac;
#pragma unroll
        for (int j = 0; j < 4; j++)
            g_ytmp[pbase + j * 4] = rna_tf32(yv[j] + half_dt * kv[j]);
    } else if (mode == 1 || mode == 2) {
        float4 ac = *reinterpret_cast<const float4*>(&g_acc[i]);
        ac.x += 2.f * kv[0]; ac.y += 2.f * kv[1];
        ac.z += 2.f * kv[2]; ac.w += 2.f * kv[3];
        *reinterpret_cast<float4*>(&g_acc[i]) = ac;
        float step = (mode == 1) ? half_dt : dt;
#pragma unroll
        for (int j = 0; j < 4; j++)
            g_ytmp[pbase + j * 4] = rna_tf32(yv[j] + step * kv[j]);
    } else if (mode == 3) {
        float4 ac = *reinterpret_cast<const float4*>(&g_acc[i]);
        float acv[4] = {ac.x, ac.y, ac.z, ac.w};
        float4 yn;
        yn.x = yv[0] + sixth_dt * (acv[0] + kv[0]);
        yn.y = yv[1] + sixth_dt * (acv[1] + kv[1]);
        yn.z = yv[2] + sixth_dt * (acv[2] + kv[2]);
        yn.w = yv[3] + sixth_dt * (acv[3] + kv[3]);
        *reinterpret_cast<float4*>(&g_y[i]) = yn;
        float ynv[4] = {yn.x, yn.y, yn.z, yn.w};
#pragma unroll
        for (int j = 0; j < 4; j++)
            g_yr[pbase + j * 4] = rna_tf32(ynv[j]);
    } else {
        float4 ac = *reinterpret_cast<const float4*>(&g_acc[i]);
        float4 o;
        o.x = yv[0] + sixth_dt * (ac.x + kv[0]);
        o.y = yv[1] + sixth_dt * (ac.y + kv[1]);
        o.z = yv[2] + sixth_dt * (ac.z + kv[2]);
        o.w = yv[3] + sixth_dt * (ac.w + kv[3]);
        *reinterpret_cast<float4*>(&yout[i]) = o;
    }
}

// ---------------------------------------------------------------------------
extern "C" void kernel_launch(void* const* d_in, const int* in_sizes, int n_in,
                              void* d_out, int out_size)
{
    const float* x  = (const float*)d_in[0];   // [1024, 512]
    const float* W1 = (const float*)d_in[1];   // [512, 2048]
    const float* b1 = (const float*)d_in[2];   // [2048]
    const float* W2 = (const float*)d_in[3];   // [2048, 512]
    const float* b2 = (const float*)d_in[4];   // [512]
    float* out = (float*)d_out;                // [1024, 512]

    const float dt = 1.0f / (float)NSTEPS;

    const int SMEM_G = 24576 * 4;   // 98,304 B (3 x (16KB A + 16KB B))
    cudaFuncSetAttribute(gemm1_tanh,   cudaFuncAttributeMaxDynamicSharedMemorySize, SMEM_G);
    cudaFuncSetAttribute(gemm2_splitk, cudaFuncAttributeMaxDynamicSharedMemorySize, SMEM_G);

    init_y_kernel<<<(B_ * D_ + 255) / 256, 256>>>(x);
    prep_weights_kernel<<<(D_ * H_ + 255) / 256, 256>>>(W1, W2);

    dim3 grid1(H_ / 128, B_ / 128);        // (16,8)  = 128 CTAs
    dim3 grid2(D_ / 128, B_ / 128, 8);     // (4,8,8) = 256 CTAs
    dim3 gridE((B_ * D_ / 4) / 256);       // 512 blocks

    for (int s = 0; s < NSTEPS; s++) {
        float t = dt * (float)s;

        gemm1_tanh  <<<grid1, 256, SMEM_G>>>(b1, t, /*in_sel=*/0);
        gemm2_splitk<<<grid2, 256, SMEM_G>>>();
        rk4_epi     <<<gridE, 256>>>(b2, dt, /*mode=*/0, out);

        gemm1_tanh  <<<grid1, 256, SMEM_G>>>(b1, t + 0.5f * dt, /*in_sel=*/1);
        gemm2_splitk<<<grid2, 256, SMEM_G>>>();
        rk4_epi     <<<gridE, 256>>>(b2, dt, /*mode=*/1, out);

        gemm1_tanh  <<<grid1, 256, SMEM_G>>>(b1, t + 0.5f * dt, /*in_sel=*/1);
        gemm2_splitk<<<grid2, 256, SMEM_G>>>();
        rk4_epi     <<<gridE, 256>>>(b2, dt, /*mode=*/2, out);

        gemm1_tanh  <<<grid1, 256, SMEM_G>>>(b1, t + dt, /*in_sel=*/1);
        gemm2_splitk<<<grid2, 256, SMEM_G>>>();
        int mode = (s == NSTEPS - 1) ? 4 : 3;
        rk4_epi     <<<gridE, 256>>>(b2, dt, mode, out);
    }
}

// round 17
// speedup vs baseline: 1.5470x; 1.0182x over previous
#include <cuda_runtime.h>
#include <math.h>

// Problem dims (fixed by the reference)
#define B_  1024
#define D_  512
#define H_  2048
#define NSTEPS 16

// ============================================================================
// Packed fragment layouts (all MMA operands pre-packed by their producers):
//
// A-pack (activations, [M x K] logical):
//   tile = m>>4, k8 = k>>3, lane = (m&7)*4 + (k&3),
//   slot = ((m>>3)&1) + 2*((k>>2)&1)
//   off  = ((tile*K8 + k8)*32 + lane)*4 + slot      (K8 = K/8)
//
// B-pack (weights, [K x N] logical, col-frag):
//   ntile = n>>5, nt = (n>>3)&3, k8 = k>>3, lane = (n&7)*4 + (k&3),
//   kh = (k>>2)&1
//   off = (((ntile*K8 + k8)*4 + nt)*32 + lane)*2 + kh
// ============================================================================

// -------- device scratch (allocation-free: static __device__ globals) ------
__device__ float g_y   [B_ * D_];      // state y, row-major (exact fp32)
__device__ float g_yr  [B_ * D_];      // A-pack of rna(y), K=512
__device__ float g_ytmp[B_ * D_];      // A-pack of rna(y + c*k), K=512
__device__ float g_acc [B_ * D_];      // RK4 accumulator, row-major
__device__ float g_h   [B_ * H_];      // A-pack of rna(tanh(...)), K=2048
__device__ float g_W1p [D_ * H_];      // B-pack of rna(W1), K=512, N=2048
__device__ float g_W2p [H_ * D_];      // B-pack of rna(W2), K=2048, N=512
__device__ float g_part[4][B_ * D_];   // split-K partials, row-major (x4)

// ---------------------------------------------------------------------------
__device__ __forceinline__ float rna_tf32(float x) {
    unsigned r;
    asm("cvt.rna.tf32.f32 %0, %1;" : "=r"(r) : "f"(x));
    return __uint_as_float(r);
}
__device__ __forceinline__ float fast_tanh(float x) {
    float y;
    asm("tanh.approx.f32 %0, %1;" : "=f"(y) : "f"(x));
    return y;
}
// mma.sync m16n8k8 tf32: D = A@B + C, fp32 accumulate. Inputs tf32-exact.
__device__ __forceinline__ void mma_tf32(float* c, const unsigned* a, const unsigned* b) {
    asm volatile(
        "mma.sync.aligned.m16n8k8.row.col.f32.tf32.tf32.f32 "
        "{%0,%1,%2,%3}, {%4,%5,%6,%7}, {%8,%9}, {%0,%1,%2,%3};"
        : "+f"(c[0]), "+f"(c[1]), "+f"(c[2]), "+f"(c[3])
        : "r"(a[0]), "r"(a[1]), "r"(a[2]), "r"(a[3]),
          "r"(b[0]), "r"(b[1]));
}
__device__ __forceinline__ void cp_async16(float* smem_dst, const float* gmem_src) {
    unsigned s = (unsigned)__cvta_generic_to_shared(smem_dst);
    asm volatile("cp.async.ca.shared.global [%0], [%1], 16;\n" :: "r"(s), "l"(gmem_src));
}
__device__ __forceinline__ void cp_commit() {
    asm volatile("cp.async.commit_group;\n");
}
template <int N>
__device__ __forceinline__ void cp_wait() {
    asm volatile("cp.async.wait_group %0;\n" :: "n"(N));
}

// ---------------------------------------------------------------------------
__device__ __forceinline__ int apack_off(int m, int k, int K8) {
    int tile = m >> 4, k8 = k >> 3;
    int lane = (m & 7) * 4 + (k & 3);
    int slot = ((m >> 3) & 1) + 2 * ((k >> 2) & 1);
    return ((tile * K8 + k8) * 32 + lane) * 4 + slot;
}
__device__ __forceinline__ int bpack_off(int k, int n, int K8) {
    int ntile = n >> 5, nt = (n >> 3) & 3, k8 = k >> 3;
    int lane = (n & 7) * 4 + (k & 3);
    int kh = (k >> 2) & 1;
    return (((ntile * K8 + k8) * 4 + nt) * 32 + lane) * 2 + kh;
}

// ---------------------------------------------------------------------------
__global__ void init_y_kernel(const float* __restrict__ x) {
    int i = blockIdx.x * blockDim.x + threadIdx.x;
    if (i < B_ * D_) {
        float v = x[i];
        g_y[i] = v;
        int m = i >> 9, k = i & 511;
        g_yr[apack_off(m, k, 64)] = rna_tf32(v);
    }
}
__global__ void prep_weights_kernel(const float* __restrict__ W1,
                                    const float* __restrict__ W2) {
    int i = blockIdx.x * blockDim.x + threadIdx.x;
    if (i < D_ * H_) {
        int k1 = i >> 11, n1 = i & 2047;
        g_W1p[bpack_off(k1, n1, 64)] = rna_tf32(W1[i]);
        int k2 = i >> 9, n2 = i & 511;
        g_W2p[bpack_off(k2, n2, 256)] = rna_tf32(W2[i]);
    }
}

// ---------------------------------------------------------------------------
// SMEM (floats), dynamic 98,304 B per CTA, BK=32, both GEMMs:
//   Sa(s) at s*4096          (A slab 16KB: [8 tiles][4 k8][32 lanes] x 16B)
//   Sb(s) at 12288 + s*4096  (B slab 16KB: [4 ntl][4 k8][4 nt][32 lanes] x 8B)
#define SB0 12288

// ---------------------------------------------------------------------------
// GEMM1:  g_h = A-pack( rna( tanh( Ain @ W1 + b1 + t ) ) )
//   CTA 128x128, BK=32, 256 threads = 8 warps (2M x 4N), warp tile 64x32.
//   16 slabs. Grid (16,8) = 128 CTAs = one clean wave.
__global__ __launch_bounds__(256) void gemm1_tanh(
    const float* __restrict__ b1, float t, int in_sel)
{
    extern __shared__ float S[];

    const float* __restrict__ Ain = in_sel ? g_ytmp : g_yr;  // A-pack K8=64
    const float* __restrict__ Bw  = g_W1p;                    // B-pack K8=64

    const int tid  = threadIdx.x;
    const int lane = tid & 31;
    const int warp = tid >> 5;
    const int g    = lane >> 2;
    const int t4   = lane & 3;
    const int wm   = warp & 1;      // m offset wm*64
    const int wn   = warp >> 1;     // n offset wn*32

    const int tile0  = blockIdx.y * 8;
    const int ntile0 = blockIdx.x * 4;
    const int bn0    = blockIdx.x * 128;
    const int bm0    = blockIdx.y * 128;

    auto load_slab = [&](int k0, int s) {
        const int k8b = k0 >> 3;
#pragma unroll
        for (int i = 0; i < 4; i++) {
            int id = tid + 256 * i;
            int tl = id >> 7, k8L = (id >> 5) & 3, ln = id & 31;
            cp_async16(&S[s * 4096 + id * 4],
                       &Ain[(((tile0 + tl) * 64 + k8b + k8L) * 32 + ln) * 4]);
        }
#pragma unroll
        for (int i = 0; i < 4; i++) {
            int id = tid + 256 * i;
            int ntl = id >> 8, k8L = (id >> 6) & 3, nt = (id >> 4) & 3, ln = (id & 15) * 2;
            cp_async16(&S[SB0 + s * 4096 + id * 4],
                       &Bw[((((ntile0 + ntl) * 64 + k8b + k8L) * 4 + nt) * 32 + ln) * 2]);
        }
        cp_commit();
    };

    float c[4][4][4];
#pragma unroll
    for (int i = 0; i < 4; i++)
#pragma unroll
        for (int j = 0; j < 4; j++)
#pragma unroll
            for (int e = 0; e < 4; e++) c[i][j][e] = 0.f;

    const int NS = D_ / 32;   // 16 slabs
    load_slab(0, 0);
    load_slab(32, 1);

    for (int si = 0; si < NS; si++) {
        if (si + 1 < NS) cp_wait<1>(); else cp_wait<0>();
        __syncthreads();
        if (si + 2 < NS) load_slab((si + 2) * 32, (si + 2) % 3);

        const float* Sa = &S[(si % 3) * 4096];
        const float* Sb = &S[SB0 + (si % 3) * 4096];
#pragma unroll
        for (int k8L = 0; k8L < 4; k8L++) {
            unsigned a[4][4], b[4][2];
#pragma unroll
            for (int mt = 0; mt < 4; mt++) {
                int tile = wm * 4 + mt;
                uint4 av = *reinterpret_cast<const uint4*>(
                    &Sa[((tile * 4 + k8L) * 32 + lane) * 4]);
                a[mt][0] = av.x; a[mt][1] = av.y; a[mt][2] = av.z; a[mt][3] = av.w;
            }
#pragma unroll
            for (int nt = 0; nt < 4; nt++) {
                uint2 bv = *reinterpret_cast<const uint2*>(
                    &Sb[(((wn * 4 + k8L) * 4 + nt) * 32 + lane) * 2]);
                b[nt][0] = bv.x; b[nt][1] = bv.y;
            }
#pragma unroll
            for (int mt = 0; mt < 4; mt++)
#pragma unroll
                for (int nt = 0; nt < 4; nt++)
                    mma_tf32(c[mt][nt], a[mt], b[nt]);
        }
    }

    // epilogue: rna(tanh(c + b1 + t)) -> g_h in A-pack layout (K8=256)
#pragma unroll
    for (int mt = 0; mt < 4; mt++) {
        int row0 = bm0 + wm * 64 + mt * 16 + g;
        int tile = row0 >> 4;
#pragma unroll
        for (int nt = 0; nt < 4; nt++) {
            int col0 = bn0 + wn * 32 + nt * 8 + 2 * t4;
            int k8   = col0 >> 3;
            int kh   = (col0 >> 2) & 1;
            int ln0  = g * 4 + (col0 & 3);
            int base = ((tile * 256 + k8) * 32) * 4 + 2 * kh;
            float bb0 = b1[col0] + t, bb1 = b1[col0 + 1] + t;
            g_h[base + ln0 * 4 + 0]       = rna_tf32(fast_tanh(c[mt][nt][0] + bb0));
            g_h[base + (ln0 + 1) * 4 + 0] = rna_tf32(fast_tanh(c[mt][nt][1] + bb1));
            g_h[base + ln0 * 4 + 1]       = rna_tf32(fast_tanh(c[mt][nt][2] + bb0));
            g_h[base + (ln0 + 1) * 4 + 1] = rna_tf32(fast_tanh(c[mt][nt][3] + bb1));
        }
    }
}

// ---------------------------------------------------------------------------
// GEMM2 split-K x4 — byte-for-byte gemm1 mainloop geometry:
//   partial[z] = g_h[:, z*512:(z+1)*512] @ W2[z*512:(z+1)*512, :]
//   CTA 128x128, K-slice 512, BK=32, 16 slabs, 256 threads, warp tile 64x32.
//   Grid (4,8,4) = 128 CTAs = one clean wave.
__global__ __launch_bounds__(256) void gemm2_splitk()
{
    extern __shared__ float S[];

    const int tid  = threadIdx.x;
    const int lane = tid & 31;
    const int warp = tid >> 5;
    const int g    = lane >> 2;
    const int t4   = lane & 3;
    const int wm   = warp & 1;
    const int wn   = warp >> 1;

    const int tile0  = blockIdx.y * 8;
    const int ntile0 = blockIdx.x * 4;
    const int bn0    = blockIdx.x * 128;
    const int bm0    = blockIdx.y * 128;
    const int k8z    = blockIdx.z * 64;   // K-slice base in k8 units (512/8)

    auto load_slab = [&](int k0, int s) {
        const int k8b = k8z + (k0 >> 3);
#pragma unroll
        for (int i = 0; i < 4; i++) {
            int id = tid + 256 * i;
            int tl = id >> 7, k8L = (id >> 5) & 3, ln = id & 31;
            cp_async16(&S[s * 4096 + id * 4],
                       &g_h[(((tile0 + tl) * 256 + k8b + k8L) * 32 + ln) * 4]);
        }
#pragma unroll
        for (int i = 0; i < 4; i++) {
            int id = tid + 256 * i;
            int ntl = id >> 8, k8L = (id >> 6) & 3, nt = (id >> 4) & 3, ln = (id & 15) * 2;
            cp_async16(&S[SB0 + s * 4096 + id * 4],
                       &g_W2p[((((ntile0 + ntl) * 256 + k8b + k8L) * 4 + nt) * 32 + ln) * 2]);
        }
        cp_commit();
    };

    float c[4][4][4];
#pragma unroll
    for (int i = 0; i < 4; i++)
#pragma unroll
        for (int j = 0; j < 4; j++)
#pragma unroll
            for (int e = 0; e < 4; e++) c[i][j][e] = 0.f;

    const int NS = 512 / 32;   // 16 slabs
    load_slab(0, 0);
    load_slab(32, 1);

    for (int si = 0; si < NS; si++) {
        if (si + 1 < NS) cp_wait<1>(); else cp_wait<0>();
        __syncthreads();
        if (si + 2 < NS) load_slab((si + 2) * 32, (si + 2) % 3);

        const float* Sa = &S[(si % 3) * 4096];
        const float* Sb = &S[SB0 + (si % 3) * 4096];
#pragma unroll
        for (int k8L = 0; k8L < 4; k8L++) {
            unsigned a[4][4], b[4][2];
#pragma unroll
            for (int mt = 0; mt < 4; mt++) {
                int tile = wm * 4 + mt;
                uint4 av = *reinterpret_cast<const uint4*>(
                    &Sa[((tile * 4 + k8L) * 32 + lane) * 4]);
                a[mt][0] = av.x; a[mt][1] = av.y; a[mt][2] = av.z; a[mt][3] = av.w;
            }
#pragma unroll
            for (int nt = 0; nt < 4; nt++) {
                uint2 bv = *reinterpret_cast<const uint2*>(
                    &Sb[(((wn * 4 + k8L) * 4 + nt) * 32 + lane) * 2]);
                b[nt][0] = bv.x; b[nt][1] = bv.y;
            }
#pragma unroll
            for (int mt = 0; mt < 4; mt++)
#pragma unroll
                for (int nt = 0; nt < 4; nt++)
                    mma_tf32(c[mt][nt], a[mt], b[nt]);
        }
    }

    // write raw partial tile (row-major)
    float* __restrict__ P = g_part[blockIdx.z];
#pragma unroll
    for (int mt = 0; mt < 4; mt++) {
        int row0 = bm0 + wm * 64 + mt * 16 + g;
#pragma unroll
        for (int nt = 0; nt < 4; nt++) {
            int col = bn0 + wn * 32 + nt * 8 + 2 * t4;
            *reinterpret_cast<float2*>(&P[(size_t)row0 * D_ + col]) =
                make_float2(c[mt][nt][0], c[mt][nt][1]);
            *reinterpret_cast<float2*>(&P[(size_t)(row0 + 8) * D_ + col]) =
                make_float2(c[mt][nt][2], c[mt][nt][3]);
        }
    }
}

// ---------------------------------------------------------------------------
// RK4 epilogue: kv = sum of 4 partials + b2; apply stage update.
// g_ytmp/g_yr written in A-pack layout (K8=64).
// mode: 0 k1 / 1 k2 / 2 k3 / 3 k4 / 4 k4-final(write d_out)
__global__ __launch_bounds__(256) void rk4_epi(
    const float* __restrict__ b2, float dt, int mode, float* __restrict__ yout)
{
    const int i4 = blockIdx.x * blockDim.x + threadIdx.x;   // 0..131071
    const int i  = i4 * 4;
    const int m   = i >> 9;
    const int k   = i & 511;          // k % 4 == 0
    const int col = k;

    float kv[4] = {0.f, 0.f, 0.f, 0.f};
#pragma unroll
    for (int z = 0; z < 4; z++) {
        float4 p = *reinterpret_cast<const float4*>(&g_part[z][i]);
        kv[0] += p.x; kv[1] += p.y; kv[2] += p.z; kv[3] += p.w;
    }
    float4 bb = *reinterpret_cast<const float4*>(&b2[col]);
    kv[0] += bb.x; kv[1] += bb.y; kv[2] += bb.z; kv[3] += bb.w;

    const float half_dt  = 0.5f * dt;
    const float sixth_dt = dt * (1.0f / 6.0f);

    float4 y = *reinterpret_cast<const float4*>(&g_y[i]);
    float yv[4] = {y.x, y.y, y.z, y.w};

    const int pbase = (((m >> 4) * 64 + (k >> 3)) * 32 + (m & 7) * 4) * 4
                      + ((m >> 3) & 1) + 2 * ((k >> 2) & 1);

    if (mode == 0) {
        float4 ac;
        ac.x = kv[0]; ac.y = kv[1]; ac.z = kv[2]; ac.w = kv[3];
        *reinterpret_cast<float4*>(&g_acc[i]) = ac;
#pragma unroll
        for (int j = 0; j < 4; j++)
            g_ytmp[pbase + j * 4] = rna_tf32(yv[j] + half_dt * kv[j]);
    } else if (mode == 1 || mode == 2) {
        float4 ac = *reinterpret_cast<const float4*>(&g_acc[i]);
        ac.x += 2.f * kv[0]; ac.y += 2.f * kv[1];
        ac.z += 2.f * kv[2]; ac.w += 2.f * kv[3];
        *reinterpret_cast<float4*>(&g_acc[i]) = ac;
        float step = (mode == 1) ? half_dt : dt;
#pragma unroll
        for (int j = 0; j < 4; j++)
            g_ytmp[pbase + j * 4] = rna_tf32(yv[j] + step * kv[j]);
    } else if (mode == 3) {
        float4 ac = *reinterpret_cast<const float4*>(&g_acc[i]);
        float acv[4] = {ac.x, ac.y, ac.z, ac.w};
        float4 yn;
        yn.x = yv[0] + sixth_dt * (acv[0] + kv[0]);
        yn.y = yv[1] + sixth_dt * (acv[1] + kv[1]);
        yn.z = yv[2] + sixth_dt * (acv[2] + kv[2]);
        yn.w = yv[3] + sixth_dt * (acv[3] + kv[3]);
        *reinterpret_cast<float4*>(&g_y[i]) = yn;
        float ynv[4] = {yn.x, yn.y, yn.z, yn.w};
#pragma unroll
        for (int j = 0; j < 4; j++)
            g_yr[pbase + j * 4] = rna_tf32(ynv[j]);
    } else {
        float4 ac = *reinterpret_cast<const float4*>(&g_acc[i]);
        float4 o;
        o.x = yv[0] + sixth_dt * (ac.x + kv[0]);
        o.y = yv[1] + sixth_dt * (ac.y + kv[1]);
        o.z = yv[2] + sixth_dt * (ac.z + kv[2]);
        o.w = yv[3] + sixth_dt * (ac.w + kv[3]);
        *reinterpret_cast<float4*>(&yout[i]) = o;
    }
}

// ---------------------------------------------------------------------------
extern "C" void kernel_launch(void* const* d_in, const int* in_sizes, int n_in,
                              void* d_out, int out_size)
{
    const float* x  = (const float*)d_in[0];   // [1024, 512]
    const float* W1 = (const float*)d_in[1];   // [512, 2048]
    const float* b1 = (const float*)d_in[2];   // [2048]
    const float* W2 = (const float*)d_in[3];   // [2048, 512]
    const float* b2 = (const float*)d_in[4];   // [512]
    float* out = (float*)d_out;                // [1024, 512]

    const float dt = 1.0f / (float)NSTEPS;

    const int SMEM_G = 24576 * 4;   // 98,304 B (3 x (16KB A + 16KB B))
    cudaFuncSetAttribute(gemm1_tanh,   cudaFuncAttributeMaxDynamicSharedMemorySize, SMEM_G);
    cudaFuncSetAttribute(gemm2_splitk, cudaFuncAttributeMaxDynamicSharedMemorySize, SMEM_G);

    init_y_kernel<<<(B_ * D_ + 255) / 256, 256>>>(x);
    prep_weights_kernel<<<(D_ * H_ + 255) / 256, 256>>>(W1, W2);

    dim3 grid1(H_ / 128, B_ / 128);        // (16,8)  = 128 CTAs, one wave
    dim3 grid2(D_ / 128, B_ / 128, 4);     // (4,8,4) = 128 CTAs, one wave
    dim3 gridE((B_ * D_ / 4) / 256);       // 512 blocks

    for (int s = 0; s < NSTEPS; s++) {
        float t = dt * (float)s;

        gemm1_tanh  <<<grid1, 256, SMEM_G>>>(b1, t, /*in_sel=*/0);
        gemm2_splitk<<<grid2, 256, SMEM_G>>>();
        rk4_epi     <<<gridE, 256>>>(b2, dt, /*mode=*/0, out);

        gemm1_tanh  <<<grid1, 256, SMEM_G>>>(b1, t + 0.5f * dt, /*in_sel=*/1);
        gemm2_splitk<<<grid2, 256, SMEM_G>>>();
        rk4_epi     <<<gridE, 256>>>(b2, dt, /*mode=*/1, out);

        gemm1_tanh  <<<grid1, 256, SMEM_G>>>(b1, t + 0.5f * dt, /*in_sel=*/1);
        gemm2_splitk<<<grid2, 256, SMEM_G>>>();
        rk4_epi     <<<gridE, 256>>>(b2, dt, /*mode=*/2, out);

        gemm1_tanh  <<<grid1, 256, SMEM_G>>>(b1, t + dt, /*in_sel=*/1);
        gemm2_splitk<<<grid2, 256, SMEM_G>>>();
        int mode = (s == NSTEPS - 1) ? 4 : 3;
        rk4_epi     <<<gridE, 256>>>(b2, dt, mode, out);
    }
}